// round 6
// baseline (speedup 1.0000x reference)
#include <cuda_runtime.h>
#include <cuda_fp16.h>

#define NN 100000
#define EE 1600000
#define BB 64
#define EPS_MSG 1e-7f
#define ENC_NEGINF 0x007FFFFFu

// ---------------- scratch (static __device__, no allocations) ----------------
__device__ float  g_h[NN * 64];        // node state h (fp32)
__device__ __half g_hmsg[NN * 64];     // relu(h)+eps messages (fp16)
__device__ float  g_hidden[NN * 128];  // MLP hidden (reused as [N,12] for layer 0)
__device__ float  g_x8[NN * 8];        // relu(x)+eps padded to 8 (layer-0 messages)
__device__ int    g_deg[NN];
__device__ int    g_tmp[NN];
__device__ int    g_rowptr[NN + 1];
__device__ int    g_pos[NN];
__device__ int    g_col[EE];
__device__ int    g_bsum[128];
__device__ float  g_psum[2048 * 128];
__device__ float  g_psumsq[2048 * 128];
__device__ float  g_scale[128];
__device__ float  g_shift[128];
__device__ unsigned g_pool[BB * 64];
__device__ int    g_ctr;   // last-block counter (reset by last block each use)

#define SMEM_AG ((128 * 68 + 64 * 132) * 4)

// ---------------- helpers ----------------
__device__ __forceinline__ unsigned encf(float f) {
    unsigned u = __float_as_uint(f);
    return (u & 0x80000000u) ? ~u : (u | 0x80000000u);
}
__device__ __forceinline__ float decf(unsigned u) {
    return __uint_as_float((u & 0x80000000u) ? (u ^ 0x80000000u) : ~u);
}
__device__ __forceinline__ float f2tf(float x) {
    unsigned r;
    asm("cvt.rna.tf32.f32 %0, %1;" : "=r"(r) : "f"(x));
    return __uint_as_float(r);
}
__device__ __forceinline__ void mma_tf32(float* d, unsigned a0, unsigned a1,
                                         unsigned a2, unsigned a3,
                                         unsigned b0, unsigned b1) {
    asm volatile(
        "mma.sync.aligned.m16n8k8.row.col.f32.tf32.tf32.f32 "
        "{%0,%1,%2,%3}, {%4,%5,%6,%7}, {%8,%9}, {%0,%1,%2,%3};"
        : "+f"(d[0]), "+f"(d[1]), "+f"(d[2]), "+f"(d[3])
        : "r"(a0), "r"(a1), "r"(a2), "r"(a3), "r"(b0), "r"(b1));
}

// ---------------- init: zero deg/pool, build padded layer-0 messages ----------------
__global__ void k_init(const float* __restrict__ x) {
    int i = blockIdx.x * blockDim.x + threadIdx.x;
    if (i < NN) {
        g_deg[i] = 0;
        float4 a, b;
        a.x = fmaxf(x[i * 6 + 0], 0.f) + EPS_MSG;
        a.y = fmaxf(x[i * 6 + 1], 0.f) + EPS_MSG;
        a.z = fmaxf(x[i * 6 + 2], 0.f) + EPS_MSG;
        a.w = fmaxf(x[i * 6 + 3], 0.f) + EPS_MSG;
        b.x = fmaxf(x[i * 6 + 4], 0.f) + EPS_MSG;
        b.y = fmaxf(x[i * 6 + 5], 0.f) + EPS_MSG;
        b.z = 0.f; b.w = 0.f;
        ((float4*)g_x8)[i * 2] = a;
        ((float4*)g_x8)[i * 2 + 1] = b;
    }
    if (i < BB * 64) g_pool[i] = ENC_NEGINF;
}

// ---------------- CSR build ----------------
__global__ void k_deg(const int* __restrict__ dst) {
    int e = blockIdx.x * blockDim.x + threadIdx.x;
    if (e < EE) atomicAdd(&g_deg[dst[e]], 1);
}

__global__ void __launch_bounds__(1024) k_scan1() {
    __shared__ int s[1024];
    int t = threadIdx.x;
    int idx = blockIdx.x * 1024 + t;
    int v = (idx < NN) ? g_deg[idx] : 0;
    s[t] = v;
    __syncthreads();
    for (int off = 1; off < 1024; off <<= 1) {
        int a = (t >= off) ? s[t - off] : 0;
        __syncthreads();
        s[t] += a;
        __syncthreads();
    }
    if (idx < NN) g_tmp[idx] = s[t];
    if (t == 1023) g_bsum[blockIdx.x] = s[1023];
}

// scan of 98 block sums fused into the apply pass
__global__ void k_scan3() {
    __shared__ int s[128];
    int t = threadIdx.x;
    if (t < 128) s[t] = (t < 98) ? g_bsum[t] : 0;
    __syncthreads();
    for (int off = 1; off < 128; off <<= 1) {
        int a = (t >= off && t < 128) ? s[t - off] : 0;
        __syncthreads();
        if (t < 128) s[t] += a;
        __syncthreads();
    }
    int idx = blockIdx.x * blockDim.x + t;
    if (idx >= NN) return;
    int b = idx >> 10;
    int off = (b > 0) ? s[b - 1] : 0;
    int incl = g_tmp[idx] + off;
    g_rowptr[idx + 1] = incl;
    g_pos[idx] = incl - g_deg[idx];
    if (idx == 0) g_rowptr[0] = 0;
}

__global__ void k_scatter(const int* __restrict__ src, const int* __restrict__ dst) {
    int e = blockIdx.x * blockDim.x + threadIdx.x;
    if (e >= EE) return;
    int p = atomicAdd(&g_pos[dst[e]], 1);
    g_col[p] = src[e];
}

// ---------------- layer 0: agg(F=6, shift-free softmax) + MLP1 (6->12) + BN ----------------
__global__ void __launch_bounds__(256) k_l0(const float* __restrict__ x,
                                            const float* __restrict__ w1,
                                            const float* __restrict__ b1,
                                            const float* __restrict__ gam,
                                            const float* __restrict__ bet) {
    __shared__ float w_s[72];
    __shared__ float sacc[12], sacc2[12];
    __shared__ int isLast;
    int t = threadIdx.x;
    if (t < 72) w_s[t] = w1[t];
    if (t < 12) { sacc[t] = 0.f; sacc2[t] = 0.f; }
    __syncthreads();

    int n = blockIdx.x * 256 + t;
    float hid[12];
#pragma unroll
    for (int j = 0; j < 12; j++) hid[j] = 0.f;

    if (n < NN) {
        int beg = g_rowptr[n], end = g_rowptr[n + 1];
        float p[6], q[6];
#pragma unroll
        for (int c = 0; c < 6; c++) { p[c] = 0.f; q[c] = 0.f; }
        const float4* __restrict__ X8 = (const float4*)g_x8;
        for (int e = beg; e < end; e++) {
            int s = g_col[e];
            float4 v0 = X8[s * 2];
            float4 v1 = X8[s * 2 + 1];
            float ex;
            ex = __expf(v0.x); p[0] += ex; q[0] = fmaf(v0.x, ex, q[0]);
            ex = __expf(v0.y); p[1] += ex; q[1] = fmaf(v0.y, ex, q[1]);
            ex = __expf(v0.z); p[2] += ex; q[2] = fmaf(v0.z, ex, q[2]);
            ex = __expf(v0.w); p[3] += ex; q[3] = fmaf(v0.w, ex, q[3]);
            ex = __expf(v1.x); p[4] += ex; q[4] = fmaf(v1.x, ex, q[4]);
            ex = __expf(v1.y); p[5] += ex; q[5] = fmaf(v1.y, ex, q[5]);
        }
        float o[6];
#pragma unroll
        for (int c = 0; c < 6; c++) o[c] = q[c] / (p[c] + 1e-16f) + x[n * 6 + c];
#pragma unroll
        for (int j = 0; j < 12; j++) {
            float a = b1[j];
#pragma unroll
            for (int c = 0; c < 6; c++) a = fmaf(o[c], w_s[c * 12 + j], a);
            hid[j] = a;
            g_hidden[n * 12 + j] = a;
        }
    }
#pragma unroll
    for (int j = 0; j < 12; j++) {
        float v = hid[j], v2 = v * v;
        for (int off = 16; off; off >>= 1) {
            v += __shfl_down_sync(0xffffffffu, v, off);
            v2 += __shfl_down_sync(0xffffffffu, v2, off);
        }
        if ((t & 31) == 0) { atomicAdd(&sacc[j], v); atomicAdd(&sacc2[j], v2); }
    }
    __syncthreads();
    if (t < 12) {
        g_psum[blockIdx.x * 12 + t] = sacc[t];
        g_psumsq[blockIdx.x * 12 + t] = sacc2[t];
    }
    __threadfence();
    if (t == 0) isLast = (atomicAdd(&g_ctr, 1) == (int)gridDim.x - 1);
    __syncthreads();
    if (isLast) {
        if (t == 0) g_ctr = 0;
        if (t < 12) {
            float s = 0.f, s2 = 0.f;
            for (int i = 0; i < (int)gridDim.x; i++) {
                s += g_psum[i * 12 + t];
                s2 += g_psumsq[i * 12 + t];
            }
            float mu = s / (float)NN;
            float var = fmaxf(s2 / (float)NN - mu * mu, 0.f);
            float sc = gam[t] * rsqrtf(var + 1e-5f);
            g_scale[t] = sc;
            g_shift[t] = bet[t] - mu * sc;
        }
    }
}

// ---------------- layer 0 MLP2: h = relu(.); also emit fp16 messages ----------------
__global__ void __launch_bounds__(256) k_l0_mlp2(const float* __restrict__ w2,
                                                 const float* __restrict__ b2) {
    __shared__ float w_s[12 * 64];
    __shared__ float b_s[64];
    int t = threadIdx.x;
    for (int i = t; i < 768; i += 256) w_s[i] = w2[i];
    if (t < 64) b_s[t] = b2[t];
    __syncthreads();
    int n = blockIdx.x * 256 + t;
    if (n >= NN) return;
    float v[12];
#pragma unroll
    for (int j = 0; j < 12; j++)
        v[j] = fmaxf(fmaf(g_hidden[n * 12 + j], g_scale[j], g_shift[j]), 0.f);
    for (int c0 = 0; c0 < 64; c0 += 4) {
        float a0 = b_s[c0], a1 = b_s[c0 + 1], a2 = b_s[c0 + 2], a3 = b_s[c0 + 3];
#pragma unroll
        for (int j = 0; j < 12; j++) {
            float vj = v[j];
            a0 = fmaf(vj, w_s[j * 64 + c0], a0);
            a1 = fmaf(vj, w_s[j * 64 + c0 + 1], a1);
            a2 = fmaf(vj, w_s[j * 64 + c0 + 2], a2);
            a3 = fmaf(vj, w_s[j * 64 + c0 + 3], a3);
        }
        float4 o;
        o.x = fmaxf(a0, 0.f); o.y = fmaxf(a1, 0.f);
        o.z = fmaxf(a2, 0.f); o.w = fmaxf(a3, 0.f);
        *(float4*)(g_h + n * 64 + c0) = o;
        *(__half2*)(g_hmsg + n * 64 + c0)     = __floats2half2_rn(o.x + EPS_MSG, o.y + EPS_MSG);
        *(__half2*)(g_hmsg + n * 64 + c0 + 2) = __floats2half2_rn(o.z + EPS_MSG, o.w + EPS_MSG);
    }
}

// ---------------- FUSED agg + GEMM1 + BN stats/finalize ----------------
// block = 128 nodes. Phase A: stage W (tf32) + per-warp aggregation of 16 nodes
// (8 lanes/edge, fp16 message gather, shift-free softmax) -> a_s (tf32).
// Phase B: tf32 mma -> g_hidden [128 cols], fused BN partial stats + last-block finalize.
__global__ void __launch_bounds__(256) k_agemm1(const float* __restrict__ W,
                                                const float* __restrict__ bias,
                                                const float* __restrict__ gam,
                                                const float* __restrict__ bet) {
    extern __shared__ float smem[];
    float* a_s = smem;               // [128][68]
    float* w_s = smem + 128 * 68;    // [64][132]
    __shared__ int isLast;
    int t = threadIdx.x, lane = t & 31, warp = t >> 5;
    int row0 = blockIdx.x * 128;

    // stage W [64][128] -> tf32
#pragma unroll
    for (int i = t; i < 2048; i += 256) {
        int kl = i >> 5, n4 = (i & 31) << 2;
        float4 v = *(const float4*)(W + kl * 128 + n4);
        float4 o;
        o.x = f2tf(v.x); o.y = f2tf(v.y); o.z = f2tf(v.z); o.w = f2tf(v.w);
        *(float4*)(w_s + kl * 132 + n4) = o;
    }

    // aggregation: warp handles rows [warp*16, warp*16+16)
    {
        int sub = lane >> 3, li = lane & 7;
        const uint4* __restrict__ M = (const uint4*)g_hmsg;  // 8 uint4 per node row
#pragma unroll 1
        for (int rr = 0; rr < 16; rr++) {
            int r = warp * 16 + rr;
            int n = row0 + r;
            if (n < NN) {
                int beg = g_rowptr[n], end = g_rowptr[n + 1];
                float p[8], q[8];
#pragma unroll
                for (int k = 0; k < 8; k++) { p[k] = 0.f; q[k] = 0.f; }
                for (int e = beg + sub; e < end; e += 4) {
                    int s = g_col[e];
                    uint4 mv = M[(size_t)s * 8 + li];
                    float2 f0 = __half22float2(*(__half2*)&mv.x);
                    float2 f1 = __half22float2(*(__half2*)&mv.y);
                    float2 f2 = __half22float2(*(__half2*)&mv.z);
                    float2 f3 = __half22float2(*(__half2*)&mv.w);
                    float ex;
                    ex = __expf(f0.x); p[0] += ex; q[0] = fmaf(f0.x, ex, q[0]);
                    ex = __expf(f0.y); p[1] += ex; q[1] = fmaf(f0.y, ex, q[1]);
                    ex = __expf(f1.x); p[2] += ex; q[2] = fmaf(f1.x, ex, q[2]);
                    ex = __expf(f1.y); p[3] += ex; q[3] = fmaf(f1.y, ex, q[3]);
                    ex = __expf(f2.x); p[4] += ex; q[4] = fmaf(f2.x, ex, q[4]);
                    ex = __expf(f2.y); p[5] += ex; q[5] = fmaf(f2.y, ex, q[5]);
                    ex = __expf(f3.x); p[6] += ex; q[6] = fmaf(f3.x, ex, q[6]);
                    ex = __expf(f3.y); p[7] += ex; q[7] = fmaf(f3.y, ex, q[7]);
                }
#pragma unroll
                for (int k = 0; k < 8; k++) {
                    p[k] += __shfl_xor_sync(0xffffffffu, p[k], 8);
                    q[k] += __shfl_xor_sync(0xffffffffu, q[k], 8);
                    p[k] += __shfl_xor_sync(0xffffffffu, p[k], 16);
                    q[k] += __shfl_xor_sync(0xffffffffu, q[k], 16);
                }
                if (sub == 0) {
                    float4 h0 = *(const float4*)(g_h + (size_t)n * 64 + li * 8);
                    float4 h1 = *(const float4*)(g_h + (size_t)n * 64 + li * 8 + 4);
                    float4 o0, o1;
                    o0.x = f2tf(q[0] / (p[0] + 1e-16f) + fmaxf(h0.x, 0.f));
                    o0.y = f2tf(q[1] / (p[1] + 1e-16f) + fmaxf(h0.y, 0.f));
                    o0.z = f2tf(q[2] / (p[2] + 1e-16f) + fmaxf(h0.z, 0.f));
                    o0.w = f2tf(q[3] / (p[3] + 1e-16f) + fmaxf(h0.w, 0.f));
                    o1.x = f2tf(q[4] / (p[4] + 1e-16f) + fmaxf(h1.x, 0.f));
                    o1.y = f2tf(q[5] / (p[5] + 1e-16f) + fmaxf(h1.y, 0.f));
                    o1.z = f2tf(q[6] / (p[6] + 1e-16f) + fmaxf(h1.z, 0.f));
                    o1.w = f2tf(q[7] / (p[7] + 1e-16f) + fmaxf(h1.w, 0.f));
                    *(float4*)(a_s + r * 68 + li * 8) = o0;
                    *(float4*)(a_s + r * 68 + li * 8 + 4) = o1;
                }
            } else if (sub == 0) {
                float4 z = make_float4(0.f, 0.f, 0.f, 0.f);
                *(float4*)(a_s + r * 68 + li * 8) = z;
                *(float4*)(a_s + r * 68 + li * 8 + 4) = z;
            }
        }
    }
    __syncthreads();

    // GEMM phase: 128x128, K=64
    int q = lane & 3, g = lane >> 2;
    int n0w = warp * 16;
    float acc[8][2][4];
#pragma unroll
    for (int i = 0; i < 8; i++)
#pragma unroll
        for (int j = 0; j < 2; j++)
#pragma unroll
            for (int k = 0; k < 4; k++) acc[i][j][k] = 0.f;

#pragma unroll
    for (int kk = 0; kk < 64; kk += 8) {
        unsigned b[2][2];
#pragma unroll
        for (int nt = 0; nt < 2; nt++) {
            int n = n0w + nt * 8 + g;
            b[nt][0] = __float_as_uint(w_s[(kk + q) * 132 + n]);
            b[nt][1] = __float_as_uint(w_s[(kk + 4 + q) * 132 + n]);
        }
#pragma unroll
        for (int mt = 0; mt < 8; mt++) {
            int r = mt * 16 + g;
            unsigned a0 = __float_as_uint(a_s[r * 68 + kk + q]);
            unsigned a1 = __float_as_uint(a_s[(r + 8) * 68 + kk + q]);
            unsigned a2 = __float_as_uint(a_s[r * 68 + kk + 4 + q]);
            unsigned a3 = __float_as_uint(a_s[(r + 8) * 68 + kk + 4 + q]);
            mma_tf32(acc[mt][0], a0, a1, a2, a3, b[0][0], b[0][1]);
            mma_tf32(acc[mt][1], a0, a1, a2, a3, b[1][0], b[1][1]);
        }
    }

    // epilogue: +bias, store, fused BN partial stats
#pragma unroll
    for (int nt = 0; nt < 2; nt++) {
        int c = n0w + nt * 8 + 2 * q;
        float2 bv = *(const float2*)(bias + c);
        float s0 = 0.f, s1 = 0.f, s20 = 0.f, s21 = 0.f;
#pragma unroll
        for (int mt = 0; mt < 8; mt++) {
            int rA = row0 + mt * 16 + g, rB = rA + 8;
            float v0 = acc[mt][nt][0] + bv.x, v1 = acc[mt][nt][1] + bv.y;
            float v2 = acc[mt][nt][2] + bv.x, v3 = acc[mt][nt][3] + bv.y;
            if (rA < NN) {
                *(float2*)(g_hidden + (size_t)rA * 128 + c) = make_float2(v0, v1);
                s0 += v0; s20 = fmaf(v0, v0, s20);
                s1 += v1; s21 = fmaf(v1, v1, s21);
            }
            if (rB < NN) {
                *(float2*)(g_hidden + (size_t)rB * 128 + c) = make_float2(v2, v3);
                s0 += v2; s20 = fmaf(v2, v2, s20);
                s1 += v3; s21 = fmaf(v3, v3, s21);
            }
        }
#pragma unroll
        for (int off = 16; off >= 4; off >>= 1) {
            s0 += __shfl_down_sync(0xffffffffu, s0, off);
            s1 += __shfl_down_sync(0xffffffffu, s1, off);
            s20 += __shfl_down_sync(0xffffffffu, s20, off);
            s21 += __shfl_down_sync(0xffffffffu, s21, off);
        }
        if (lane < 4) {
            int cc = n0w + nt * 8 + 2 * lane;
            g_psum[blockIdx.x * 128 + cc] = s0;
            g_psum[blockIdx.x * 128 + cc + 1] = s1;
            g_psumsq[blockIdx.x * 128 + cc] = s20;
            g_psumsq[blockIdx.x * 128 + cc + 1] = s21;
        }
    }
    __threadfence();
    if (t == 0) isLast = (atomicAdd(&g_ctr, 1) == (int)gridDim.x - 1);
    __syncthreads();
    if (isLast) {
        if (t == 0) g_ctr = 0;
        if (t < 128) {
            float s = 0.f, s2 = 0.f;
            int nb = (int)gridDim.x;
#pragma unroll 4
            for (int i = 0; i < nb; i++) {
                s += g_psum[i * 128 + t];
                s2 += g_psumsq[i * 128 + t];
            }
            float mu = s / (float)NN;
            float var = fmaxf(s2 / (float)NN - mu * mu, 0.f);
            float sc = gam[t] * rsqrtf(var + 1e-5f);
            g_scale[t] = sc;
            g_shift[t] = bet[t] - mu * sc;
        }
    }
}

// ---------------- GEMM2 (tf32 mma): relu(bn(g_hidden)) @ W[128,64] + b; h += .; emit msgs
__global__ void __launch_bounds__(256) k_gemm2(const float* __restrict__ W,
                                               const float* __restrict__ bias) {
    __shared__ float a_s[128 * 36];   // [row][k] stride 36
    __shared__ float w_s[32 * 68];    // [k][n] stride 68
    int t = threadIdx.x, lane = t & 31, warp = t >> 5;
    int q = lane & 3, g = lane >> 2;
    int row0 = blockIdx.x * 128;
    int n0w = warp * 8;
    float acc[8][4];
#pragma unroll
    for (int i = 0; i < 8; i++)
#pragma unroll
        for (int k = 0; k < 4; k++) acc[i][k] = 0.f;

    for (int kc = 0; kc < 128; kc += 32) {
#pragma unroll
        for (int i = t; i < 1024; i += 256) {
            int r = i >> 3, kk = (i & 7) << 2;
            int row = row0 + r;
            float4 o = make_float4(0.f, 0.f, 0.f, 0.f);
            if (row < NN) {
                float4 hv = *(const float4*)(g_hidden + (size_t)row * 128 + kc + kk);
                float4 sc = *(const float4*)(g_scale + kc + kk);
                float4 sh = *(const float4*)(g_shift + kc + kk);
                o.x = f2tf(fmaxf(fmaf(hv.x, sc.x, sh.x), 0.f));
                o.y = f2tf(fmaxf(fmaf(hv.y, sc.y, sh.y), 0.f));
                o.z = f2tf(fmaxf(fmaf(hv.z, sc.z, sh.z), 0.f));
                o.w = f2tf(fmaxf(fmaf(hv.w, sc.w, sh.w), 0.f));
            }
            *(float4*)(a_s + r * 36 + kk) = o;
        }
#pragma unroll
        for (int i = t; i < 512; i += 256) {
            int kl = i >> 4, n4 = (i & 15) << 2;
            float4 v = *(const float4*)(W + (kc + kl) * 64 + n4);
            float4 o;
            o.x = f2tf(v.x); o.y = f2tf(v.y); o.z = f2tf(v.z); o.w = f2tf(v.w);
            *(float4*)(w_s + kl * 68 + n4) = o;
        }
        __syncthreads();
#pragma unroll
        for (int kk = 0; kk < 32; kk += 8) {
            int n = n0w + g;
            unsigned b0 = __float_as_uint(w_s[(kk + q) * 68 + n]);
            unsigned b1 = __float_as_uint(w_s[(kk + 4 + q) * 68 + n]);
#pragma unroll
            for (int mt = 0; mt < 8; mt++) {
                int r = mt * 16 + g;
                unsigned a0 = __float_as_uint(a_s[r * 36 + kk + q]);
                unsigned a1 = __float_as_uint(a_s[(r + 8) * 36 + kk + q]);
                unsigned a2 = __float_as_uint(a_s[r * 36 + kk + 4 + q]);
                unsigned a3 = __float_as_uint(a_s[(r + 8) * 36 + kk + 4 + q]);
                mma_tf32(acc[mt], a0, a1, a2, a3, b0, b1);
            }
        }
        __syncthreads();
    }
    int c = n0w + 2 * q;
    float2 bv = *(const float2*)(bias + c);
#pragma unroll
    for (int mt = 0; mt < 8; mt++) {
        int rA = row0 + mt * 16 + g, rB = rA + 8;
        if (rA < NN) {
            float2 hv = *(float2*)(g_h + (size_t)rA * 64 + c);
            hv.x += acc[mt][0] + bv.x;
            hv.y += acc[mt][1] + bv.y;
            *(float2*)(g_h + (size_t)rA * 64 + c) = hv;
            *(__half2*)(g_hmsg + (size_t)rA * 64 + c) =
                __floats2half2_rn(fmaxf(hv.x, 0.f) + EPS_MSG, fmaxf(hv.y, 0.f) + EPS_MSG);
        }
        if (rB < NN) {
            float2 hv = *(float2*)(g_h + (size_t)rB * 64 + c);
            hv.x += acc[mt][2] + bv.x;
            hv.y += acc[mt][3] + bv.y;
            *(float2*)(g_h + (size_t)rB * 64 + c) = hv;
            *(__half2*)(g_hmsg + (size_t)rB * 64 + c) =
                __floats2half2_rn(fmaxf(hv.x, 0.f) + EPS_MSG, fmaxf(hv.y, 0.f) + EPS_MSG);
        }
    }
}

// ---------------- pool: run-length max over sorted batch + encoded atomicMax ----------------
__global__ void __launch_bounds__(256) k_pool(const int* __restrict__ batch) {
    int t = threadIdx.x;
    int c = t & 63, sub = t >> 6;
    int n0 = blockIdx.x * 64 + sub * 16;
    float cur = -__int_as_float(0x7f800000);  // -inf
    int curb = -1;
    for (int i = 0; i < 16; i++) {
        int n = n0 + i;
        if (n >= NN) break;
        int b = batch[n];
        if (b != curb) {
            if (curb >= 0) atomicMax(&g_pool[curb * 64 + c], encf(cur));
            curb = b;
            cur = -__int_as_float(0x7f800000);
        }
        cur = fmaxf(cur, g_h[n * 64 + c]);
    }
    if (curb >= 0) atomicMax(&g_pool[curb * 64 + c], encf(cur));
}

// ---------------- final MLP: [64,64] -> relu -> [64,80] ----------------
__global__ void __launch_bounds__(256) k_final(const float* __restrict__ w1,
                                               const float* __restrict__ b1,
                                               const float* __restrict__ w2,
                                               const float* __restrict__ b2,
                                               float* __restrict__ out) {
    __shared__ float g_s[64 * 64];
    __shared__ float t_s[64 * 64];
    int t = threadIdx.x;
    for (int i = t; i < 4096; i += 256) {
        unsigned u = g_pool[i];
        g_s[i] = (u == ENC_NEGINF) ? 0.f : decf(u);
    }
    __syncthreads();
    for (int e = t; e < 4096; e += 256) {
        int r = e >> 6, c = e & 63;
        float a = b1[c];
        for (int k = 0; k < 64; k++) a = fmaf(g_s[r * 64 + k], w1[k * 64 + c], a);
        t_s[e] = fmaxf(a, 0.f);
    }
    __syncthreads();
    for (int e = t; e < 5120; e += 256) {
        int r = e / 80, c = e % 80;
        float a = b2[c];
        for (int k = 0; k < 64; k++) a = fmaf(t_s[r * 64 + k], w2[k * 80 + c], a);
        out[e] = a;
    }
}

// ---------------- launch ----------------
extern "C" void kernel_launch(void* const* d_in, const int* in_sizes, int n_in,
                              void* d_out, int out_size) {
    const float* x    = (const float*)d_in[0];
    const int*   ei   = (const int*)d_in[1];
    const int*   batch = (const int*)d_in[2];
    const float* cw1  = (const float*)d_in[3];
    const float* cb1  = (const float*)d_in[4];
    const float* cg1  = (const float*)d_in[5];
    const float* cbe1 = (const float*)d_in[6];
    const float* cw2  = (const float*)d_in[7];
    const float* cb2  = (const float*)d_in[8];
    const float* Lw1  = (const float*)d_in[9];
    const float* Lb1  = (const float*)d_in[10];
    const float* Lg1  = (const float*)d_in[11];
    const float* Lbe1 = (const float*)d_in[12];
    const float* Lw2  = (const float*)d_in[13];
    const float* Lb2  = (const float*)d_in[14];
    const float* mw1  = (const float*)d_in[15];
    const float* mb1  = (const float*)d_in[16];
    const float* mw2  = (const float*)d_in[17];
    const float* mb2  = (const float*)d_in[18];
    float* out = (float*)d_out;

    const int* src = ei;
    const int* dst = ei + EE;

    cudaFuncSetAttribute(k_agemm1, cudaFuncAttributeMaxDynamicSharedMemorySize, SMEM_AG);

    // CSR build
    k_init<<<391, 256>>>(x);
    k_deg<<<EE / 256, 256>>>(dst);
    k_scan1<<<98, 1024>>>();
    k_scan3<<<391, 256>>>();
    k_scatter<<<EE / 256, 256>>>(src, dst);

    // layer 0 (6 -> 12 -> 64), h = relu(genconv(x))
    k_l0<<<391, 256>>>(x, cw1, cb1, cg1, cbe1);
    k_l0_mlp2<<<391, 256>>>(cw2, cb2);

    // layers 1..3: h += genconv(relu(h))
    for (int i = 0; i < 3; i++) {
        k_agemm1<<<782, 256, SMEM_AG>>>(Lw1 + i * 64 * 128, Lb1 + i * 128,
                                        Lg1 + i * 128, Lbe1 + i * 128);
        k_gemm2<<<782, 256>>>(Lw2 + i * 128 * 64, Lb2 + i * 64);
    }

    k_pool<<<1563, 256>>>(batch);
    k_final<<<1, 256>>>(mw1, mb1, mw2, mb2, out);
}

// round 7
// speedup vs baseline: 1.1536x; 1.1536x over previous
#include <cuda_runtime.h>
#include <cuda_fp16.h>

#define NN 100000
#define EE 1600000
#define BB 64
#define EPS_MSG 1e-7f
#define ENC_NEGINF 0x007FFFFFu

// ---------------- scratch (static __device__, no allocations) ----------------
__device__ float  g_h[NN * 64];        // node state h (fp32)
__device__ __half g_hmsg[NN * 64];     // relu(h)+eps messages (fp16)
__device__ float  g_out64[NN * 64];    // agg + residual (GEMM1 input)
__device__ float  g_hidden[NN * 128];  // MLP hidden (reused as [N,12] for layer 0)
__device__ float  g_x8[NN * 8];        // relu(x)+eps padded to 8 (layer-0 messages)
__device__ int    g_deg[NN];
__device__ int    g_tmp[NN];
__device__ int    g_rowptr[NN + 1];
__device__ int    g_pos[NN];
__device__ int    g_col[EE];
__device__ int    g_bsum[128];
__device__ float  g_psum[2048 * 128];
__device__ float  g_psumsq[2048 * 128];
__device__ float  g_scale[128];
__device__ float  g_shift[128];
__device__ unsigned g_pool[BB * 64];
__device__ int    g_ctr;   // last-block counter (reset by last block each use)

// ---------------- helpers ----------------
__device__ __forceinline__ unsigned encf(float f) {
    unsigned u = __float_as_uint(f);
    return (u & 0x80000000u) ? ~u : (u | 0x80000000u);
}
__device__ __forceinline__ float decf(unsigned u) {
    return __uint_as_float((u & 0x80000000u) ? (u ^ 0x80000000u) : ~u);
}
__device__ __forceinline__ float f2tf(float x) {
    unsigned r;
    asm("cvt.rna.tf32.f32 %0, %1;" : "=r"(r) : "f"(x));
    return __uint_as_float(r);
}
__device__ __forceinline__ void mma_tf32(float* d, unsigned a0, unsigned a1,
                                         unsigned a2, unsigned a3,
                                         unsigned b0, unsigned b1) {
    asm volatile(
        "mma.sync.aligned.m16n8k8.row.col.f32.tf32.tf32.f32 "
        "{%0,%1,%2,%3}, {%4,%5,%6,%7}, {%8,%9}, {%0,%1,%2,%3};"
        : "+f"(d[0]), "+f"(d[1]), "+f"(d[2]), "+f"(d[3])
        : "r"(a0), "r"(a1), "r"(a2), "r"(a3), "r"(b0), "r"(b1));
}

#define EXP8(f0, f1, f2, f3)                                              \
    do {                                                                  \
        float ex;                                                         \
        ex = __expf(f0.x); p[0] += ex; q[0] = fmaf(f0.x, ex, q[0]);       \
        ex = __expf(f0.y); p[1] += ex; q[1] = fmaf(f0.y, ex, q[1]);       \
        ex = __expf(f1.x); p[2] += ex; q[2] = fmaf(f1.x, ex, q[2]);       \
        ex = __expf(f1.y); p[3] += ex; q[3] = fmaf(f1.y, ex, q[3]);       \
        ex = __expf(f2.x); p[4] += ex; q[4] = fmaf(f2.x, ex, q[4]);       \
        ex = __expf(f2.y); p[5] += ex; q[5] = fmaf(f2.y, ex, q[5]);       \
        ex = __expf(f3.x); p[6] += ex; q[6] = fmaf(f3.x, ex, q[6]);       \
        ex = __expf(f3.y); p[7] += ex; q[7] = fmaf(f3.y, ex, q[7]);       \
    } while (0)

// ---------------- init: zero deg/pool, build padded layer-0 messages ----------------
__global__ void k_init(const float* __restrict__ x) {
    int i = blockIdx.x * blockDim.x + threadIdx.x;
    if (i < NN) {
        g_deg[i] = 0;
        float4 a, b;
        a.x = fmaxf(x[i * 6 + 0], 0.f) + EPS_MSG;
        a.y = fmaxf(x[i * 6 + 1], 0.f) + EPS_MSG;
        a.z = fmaxf(x[i * 6 + 2], 0.f) + EPS_MSG;
        a.w = fmaxf(x[i * 6 + 3], 0.f) + EPS_MSG;
        b.x = fmaxf(x[i * 6 + 4], 0.f) + EPS_MSG;
        b.y = fmaxf(x[i * 6 + 5], 0.f) + EPS_MSG;
        b.z = 0.f; b.w = 0.f;
        ((float4*)g_x8)[i * 2] = a;
        ((float4*)g_x8)[i * 2 + 1] = b;
    }
    if (i < BB * 64) g_pool[i] = ENC_NEGINF;
}

// ---------------- CSR build ----------------
__global__ void k_deg(const int* __restrict__ dst) {
    int e = blockIdx.x * blockDim.x + threadIdx.x;
    if (e < EE) atomicAdd(&g_deg[dst[e]], 1);
}

__global__ void __launch_bounds__(1024) k_scan1() {
    __shared__ int s[1024];
    int t = threadIdx.x;
    int idx = blockIdx.x * 1024 + t;
    int v = (idx < NN) ? g_deg[idx] : 0;
    s[t] = v;
    __syncthreads();
    for (int off = 1; off < 1024; off <<= 1) {
        int a = (t >= off) ? s[t - off] : 0;
        __syncthreads();
        s[t] += a;
        __syncthreads();
    }
    if (idx < NN) g_tmp[idx] = s[t];
    if (t == 1023) g_bsum[blockIdx.x] = s[1023];
}

// scan of 98 block sums fused into the apply pass
__global__ void k_scan3() {
    __shared__ int s[128];
    int t = threadIdx.x;
    if (t < 128) s[t] = (t < 98) ? g_bsum[t] : 0;
    __syncthreads();
    for (int off = 1; off < 128; off <<= 1) {
        int a = (t >= off && t < 128) ? s[t - off] : 0;
        __syncthreads();
        if (t < 128) s[t] += a;
        __syncthreads();
    }
    int idx = blockIdx.x * blockDim.x + t;
    if (idx >= NN) return;
    int b = idx >> 10;
    int off = (b > 0) ? s[b - 1] : 0;
    int incl = g_tmp[idx] + off;
    g_rowptr[idx + 1] = incl;
    g_pos[idx] = incl - g_deg[idx];
    if (idx == 0) g_rowptr[0] = 0;
}

__global__ void k_scatter(const int* __restrict__ src, const int* __restrict__ dst) {
    int e = blockIdx.x * blockDim.x + threadIdx.x;
    if (e >= EE) return;
    int p = atomicAdd(&g_pos[dst[e]], 1);
    g_col[p] = src[e];
}

// ---------------- layer 0: agg(F=6, shift-free softmax) + MLP1 (6->12) + BN ----------------
__global__ void __launch_bounds__(256) k_l0(const float* __restrict__ x,
                                            const float* __restrict__ w1,
                                            const float* __restrict__ b1,
                                            const float* __restrict__ gam,
                                            const float* __restrict__ bet) {
    __shared__ float w_s[72];
    __shared__ float sacc[12], sacc2[12];
    __shared__ int isLast;
    int t = threadIdx.x;
    if (t < 72) w_s[t] = w1[t];
    if (t < 12) { sacc[t] = 0.f; sacc2[t] = 0.f; }
    __syncthreads();

    int n = blockIdx.x * 256 + t;
    float hid[12];
#pragma unroll
    for (int j = 0; j < 12; j++) hid[j] = 0.f;

    if (n < NN) {
        int beg = g_rowptr[n], end = g_rowptr[n + 1];
        float p[6], q[6];
#pragma unroll
        for (int c = 0; c < 6; c++) { p[c] = 0.f; q[c] = 0.f; }
        const float4* __restrict__ X8 = (const float4*)g_x8;
        for (int e = beg; e < end; e++) {
            int s = g_col[e];
            float4 v0 = X8[s * 2];
            float4 v1 = X8[s * 2 + 1];
            float ex;
            ex = __expf(v0.x); p[0] += ex; q[0] = fmaf(v0.x, ex, q[0]);
            ex = __expf(v0.y); p[1] += ex; q[1] = fmaf(v0.y, ex, q[1]);
            ex = __expf(v0.z); p[2] += ex; q[2] = fmaf(v0.z, ex, q[2]);
            ex = __expf(v0.w); p[3] += ex; q[3] = fmaf(v0.w, ex, q[3]);
            ex = __expf(v1.x); p[4] += ex; q[4] = fmaf(v1.x, ex, q[4]);
            ex = __expf(v1.y); p[5] += ex; q[5] = fmaf(v1.y, ex, q[5]);
        }
        float o[6];
#pragma unroll
        for (int c = 0; c < 6; c++) o[c] = q[c] / (p[c] + 1e-16f) + x[n * 6 + c];
#pragma unroll
        for (int j = 0; j < 12; j++) {
            float a = b1[j];
#pragma unroll
            for (int c = 0; c < 6; c++) a = fmaf(o[c], w_s[c * 12 + j], a);
            hid[j] = a;
            g_hidden[n * 12 + j] = a;
        }
    }
#pragma unroll
    for (int j = 0; j < 12; j++) {
        float v = hid[j], v2 = v * v;
        for (int off = 16; off; off >>= 1) {
            v += __shfl_down_sync(0xffffffffu, v, off);
            v2 += __shfl_down_sync(0xffffffffu, v2, off);
        }
        if ((t & 31) == 0) { atomicAdd(&sacc[j], v); atomicAdd(&sacc2[j], v2); }
    }
    __syncthreads();
    if (t < 12) {
        g_psum[blockIdx.x * 12 + t] = sacc[t];
        g_psumsq[blockIdx.x * 12 + t] = sacc2[t];
    }
    __threadfence();
    if (t == 0) isLast = (atomicAdd(&g_ctr, 1) == (int)gridDim.x - 1);
    __syncthreads();
    if (isLast) {
        if (t == 0) g_ctr = 0;
        if (t < 12) {
            float s = 0.f, s2 = 0.f;
            for (int i = 0; i < (int)gridDim.x; i++) {
                s += g_psum[i * 12 + t];
                s2 += g_psumsq[i * 12 + t];
            }
            float mu = s / (float)NN;
            float var = fmaxf(s2 / (float)NN - mu * mu, 0.f);
            float sc = gam[t] * rsqrtf(var + 1e-5f);
            g_scale[t] = sc;
            g_shift[t] = bet[t] - mu * sc;
        }
    }
}

// ---------------- layer 0 MLP2: h = relu(.); also emit fp16 messages ----------------
__global__ void __launch_bounds__(256) k_l0_mlp2(const float* __restrict__ w2,
                                                 const float* __restrict__ b2) {
    __shared__ float w_s[12 * 64];
    __shared__ float b_s[64];
    int t = threadIdx.x;
    for (int i = t; i < 768; i += 256) w_s[i] = w2[i];
    if (t < 64) b_s[t] = b2[t];
    __syncthreads();
    int n = blockIdx.x * 256 + t;
    if (n >= NN) return;
    float v[12];
#pragma unroll
    for (int j = 0; j < 12; j++)
        v[j] = fmaxf(fmaf(g_hidden[n * 12 + j], g_scale[j], g_shift[j]), 0.f);
    for (int c0 = 0; c0 < 64; c0 += 4) {
        float a0 = b_s[c0], a1 = b_s[c0 + 1], a2 = b_s[c0 + 2], a3 = b_s[c0 + 3];
#pragma unroll
        for (int j = 0; j < 12; j++) {
            float vj = v[j];
            a0 = fmaf(vj, w_s[j * 64 + c0], a0);
            a1 = fmaf(vj, w_s[j * 64 + c0 + 1], a1);
            a2 = fmaf(vj, w_s[j * 64 + c0 + 2], a2);
            a3 = fmaf(vj, w_s[j * 64 + c0 + 3], a3);
        }
        float4 o;
        o.x = fmaxf(a0, 0.f); o.y = fmaxf(a1, 0.f);
        o.z = fmaxf(a2, 0.f); o.w = fmaxf(a3, 0.f);
        *(float4*)(g_h + n * 64 + c0) = o;
        *(__half2*)(g_hmsg + n * 64 + c0)     = __floats2half2_rn(o.x + EPS_MSG, o.y + EPS_MSG);
        *(__half2*)(g_hmsg + n * 64 + c0 + 2) = __floats2half2_rn(o.z + EPS_MSG, o.w + EPS_MSG);
    }
}

// ---------------- aggregation, F=64: warp/node, fp16 gather, shift-free softmax ------
// quarter-warp per edge: sub=lane>>3 picks edge slot (4 in flight), li=lane&7 owns
// channels [li*8, li*8+8). x2 unroll -> 8 edges per iteration, 2 LDG.128 in flight.
__global__ void __launch_bounds__(256) k_agg64() {
    int gt = blockIdx.x * blockDim.x + threadIdx.x;
    int n = gt >> 5;
    if (n >= NN) return;
    int lane = gt & 31;
    int sub = lane >> 3, li = lane & 7;
    int beg = g_rowptr[n], end = g_rowptr[n + 1];
    const uint4* __restrict__ M = (const uint4*)g_hmsg;  // 8 uint4 per node row

    float p[8], q[8];
#pragma unroll
    for (int k = 0; k < 8; k++) { p[k] = 0.f; q[k] = 0.f; }

    int e = beg + sub;
    for (; e + 4 < end; e += 8) {
        int s0 = g_col[e], s1 = g_col[e + 4];
        uint4 m0 = M[(size_t)s0 * 8 + li];
        uint4 m1 = M[(size_t)s1 * 8 + li];
        float2 a0 = __half22float2(*(__half2*)&m0.x);
        float2 a1 = __half22float2(*(__half2*)&m0.y);
        float2 a2 = __half22float2(*(__half2*)&m0.z);
        float2 a3 = __half22float2(*(__half2*)&m0.w);
        EXP8(a0, a1, a2, a3);
        float2 b0 = __half22float2(*(__half2*)&m1.x);
        float2 b1 = __half22float2(*(__half2*)&m1.y);
        float2 b2 = __half22float2(*(__half2*)&m1.z);
        float2 b3 = __half22float2(*(__half2*)&m1.w);
        EXP8(b0, b1, b2, b3);
    }
    for (; e < end; e += 4) {
        int s0 = g_col[e];
        uint4 m0 = M[(size_t)s0 * 8 + li];
        float2 a0 = __half22float2(*(__half2*)&m0.x);
        float2 a1 = __half22float2(*(__half2*)&m0.y);
        float2 a2 = __half22float2(*(__half2*)&m0.z);
        float2 a3 = __half22float2(*(__half2*)&m0.w);
        EXP8(a0, a1, a2, a3);
    }
    // merge the 4 subs (same channels, disjoint edges)
#pragma unroll
    for (int k = 0; k < 8; k++) {
        p[k] += __shfl_xor_sync(0xffffffffu, p[k], 8);
        q[k] += __shfl_xor_sync(0xffffffffu, q[k], 8);
        p[k] += __shfl_xor_sync(0xffffffffu, p[k], 16);
        q[k] += __shfl_xor_sync(0xffffffffu, q[k], 16);
    }
    if (sub == 0) {
        float4 h0 = *(const float4*)(g_h + (size_t)n * 64 + li * 8);
        float4 h1 = *(const float4*)(g_h + (size_t)n * 64 + li * 8 + 4);
        float4 o0, o1;
        o0.x = q[0] / (p[0] + 1e-16f) + fmaxf(h0.x, 0.f);
        o0.y = q[1] / (p[1] + 1e-16f) + fmaxf(h0.y, 0.f);
        o0.z = q[2] / (p[2] + 1e-16f) + fmaxf(h0.z, 0.f);
        o0.w = q[3] / (p[3] + 1e-16f) + fmaxf(h0.w, 0.f);
        o1.x = q[4] / (p[4] + 1e-16f) + fmaxf(h1.x, 0.f);
        o1.y = q[5] / (p[5] + 1e-16f) + fmaxf(h1.y, 0.f);
        o1.z = q[6] / (p[6] + 1e-16f) + fmaxf(h1.z, 0.f);
        o1.w = q[7] / (p[7] + 1e-16f) + fmaxf(h1.w, 0.f);
        *(float4*)(g_out64 + (size_t)n * 64 + li * 8) = o0;
        *(float4*)(g_out64 + (size_t)n * 64 + li * 8 + 4) = o1;
    }
}

// ---------------- GEMM1 (tf32 mma): g_out64[N,64] @ W[64,128] + b -> g_hidden[N,128]
// Fused BN partial stats + last-block finalize.
__global__ void __launch_bounds__(256) k_gemm1(const float* __restrict__ W,
                                               const float* __restrict__ bias,
                                               const float* __restrict__ gam,
                                               const float* __restrict__ bet) {
    __shared__ float a_s[128 * 36];   // [row][k] stride 36
    __shared__ float w_s[32 * 132];   // [k][n] stride 132
    __shared__ int isLast;
    int t = threadIdx.x, lane = t & 31, warp = t >> 5;
    int q = lane & 3, g = lane >> 2;
    int row0 = blockIdx.x * 128;
    int n0w = warp * 16;
    float acc[8][2][4];
#pragma unroll
    for (int i = 0; i < 8; i++)
#pragma unroll
        for (int j = 0; j < 2; j++)
#pragma unroll
            for (int k = 0; k < 4; k++) acc[i][j][k] = 0.f;

    for (int kc = 0; kc < 64; kc += 32) {
#pragma unroll
        for (int i = t; i < 1024; i += 256) {
            int r = i >> 3, kk = (i & 7) << 2;
            int row = row0 + r;
            float4 v = make_float4(0.f, 0.f, 0.f, 0.f);
            if (row < NN) v = *(const float4*)(g_out64 + row * 64 + kc + kk);
            float4 o;
            o.x = f2tf(v.x); o.y = f2tf(v.y); o.z = f2tf(v.z); o.w = f2tf(v.w);
            *(float4*)(a_s + r * 36 + kk) = o;
        }
#pragma unroll
        for (int i = t; i < 1024; i += 256) {
            int kl = i >> 5, n4 = (i & 31) << 2;
            float4 v = *(const float4*)(W + (kc + kl) * 128 + n4);
            float4 o;
            o.x = f2tf(v.x); o.y = f2tf(v.y); o.z = f2tf(v.z); o.w = f2tf(v.w);
            *(float4*)(w_s + kl * 132 + n4) = o;
        }
        __syncthreads();
#pragma unroll
        for (int kk = 0; kk < 32; kk += 8) {
            unsigned b[2][2];
#pragma unroll
            for (int nt = 0; nt < 2; nt++) {
                int n = n0w + nt * 8 + g;
                b[nt][0] = __float_as_uint(w_s[(kk + q) * 132 + n]);
                b[nt][1] = __float_as_uint(w_s[(kk + 4 + q) * 132 + n]);
            }
#pragma unroll
            for (int mt = 0; mt < 8; mt++) {
                int r = mt * 16 + g;
                unsigned a0 = __float_as_uint(a_s[r * 36 + kk + q]);
                unsigned a1 = __float_as_uint(a_s[(r + 8) * 36 + kk + q]);
                unsigned a2 = __float_as_uint(a_s[r * 36 + kk + 4 + q]);
                unsigned a3 = __float_as_uint(a_s[(r + 8) * 36 + kk + 4 + q]);
                mma_tf32(acc[mt][0], a0, a1, a2, a3, b[0][0], b[0][1]);
                mma_tf32(acc[mt][1], a0, a1, a2, a3, b[1][0], b[1][1]);
            }
        }
        __syncthreads();
    }
#pragma unroll
    for (int nt = 0; nt < 2; nt++) {
        int c = n0w + nt * 8 + 2 * q;
        float2 bv = *(const float2*)(bias + c);
        float s0 = 0.f, s1 = 0.f, s20 = 0.f, s21 = 0.f;
#pragma unroll
        for (int mt = 0; mt < 8; mt++) {
            int rA = row0 + mt * 16 + g, rB = rA + 8;
            float v0 = acc[mt][nt][0] + bv.x, v1 = acc[mt][nt][1] + bv.y;
            float v2 = acc[mt][nt][2] + bv.x, v3 = acc[mt][nt][3] + bv.y;
            if (rA < NN) {
                *(float2*)(g_hidden + (size_t)rA * 128 + c) = make_float2(v0, v1);
                s0 += v0; s20 = fmaf(v0, v0, s20);
                s1 += v1; s21 = fmaf(v1, v1, s21);
            }
            if (rB < NN) {
                *(float2*)(g_hidden + (size_t)rB * 128 + c) = make_float2(v2, v3);
                s0 += v2; s20 = fmaf(v2, v2, s20);
                s1 += v3; s21 = fmaf(v3, v3, s21);
            }
        }
#pragma unroll
        for (int off = 16; off >= 4; off >>= 1) {
            s0 += __shfl_down_sync(0xffffffffu, s0, off);
            s1 += __shfl_down_sync(0xffffffffu, s1, off);
            s20 += __shfl_down_sync(0xffffffffu, s20, off);
            s21 += __shfl_down_sync(0xffffffffu, s21, off);
        }
        if (lane < 4) {
            int cc = n0w + nt * 8 + 2 * lane;
            g_psum[blockIdx.x * 128 + cc] = s0;
            g_psum[blockIdx.x * 128 + cc + 1] = s1;
            g_psumsq[blockIdx.x * 128 + cc] = s20;
            g_psumsq[blockIdx.x * 128 + cc + 1] = s21;
        }
    }
    __threadfence();
    if (t == 0) isLast = (atomicAdd(&g_ctr, 1) == (int)gridDim.x - 1);
    __syncthreads();
    if (isLast) {
        if (t == 0) g_ctr = 0;
        if (t < 128) {
            float s = 0.f, s2 = 0.f;
            int nb = (int)gridDim.x;
#pragma unroll 4
            for (int i = 0; i < nb; i++) {
                s += g_psum[i * 128 + t];
                s2 += g_psumsq[i * 128 + t];
            }
            float mu = s / (float)NN;
            float var = fmaxf(s2 / (float)NN - mu * mu, 0.f);
            float sc = gam[t] * rsqrtf(var + 1e-5f);
            g_scale[t] = sc;
            g_shift[t] = bet[t] - mu * sc;
        }
    }
}

// ---------------- GEMM2 (tf32 mma): relu(bn(g_hidden)) @ W[128,64] + b; h += .; emit msgs
__global__ void __launch_bounds__(256) k_gemm2(const float* __restrict__ W,
                                               const float* __restrict__ bias) {
    __shared__ float a_s[128 * 36];   // [row][k] stride 36
    __shared__ float w_s[32 * 68];    // [k][n] stride 68
    int t = threadIdx.x, lane = t & 31, warp = t >> 5;
    int q = lane & 3, g = lane >> 2;
    int row0 = blockIdx.x * 128;
    int n0w = warp * 8;
    float acc[8][4];
#pragma unroll
    for (int i = 0; i < 8; i++)
#pragma unroll
        for (int k = 0; k < 4; k++) acc[i][k] = 0.f;

    for (int kc = 0; kc < 128; kc += 32) {
#pragma unroll
        for (int i = t; i < 1024; i += 256) {
            int r = i >> 3, kk = (i & 7) << 2;
            int row = row0 + r;
            float4 o = make_float4(0.f, 0.f, 0.f, 0.f);
            if (row < NN) {
                float4 hv = *(const float4*)(g_hidden + (size_t)row * 128 + kc + kk);
                float4 sc = *(const float4*)(g_scale + kc + kk);
                float4 sh = *(const float4*)(g_shift + kc + kk);
                o.x = f2tf(fmaxf(fmaf(hv.x, sc.x, sh.x), 0.f));
                o.y = f2tf(fmaxf(fmaf(hv.y, sc.y, sh.y), 0.f));
                o.z = f2tf(fmaxf(fmaf(hv.z, sc.z, sh.z), 0.f));
                o.w = f2tf(fmaxf(fmaf(hv.w, sc.w, sh.w), 0.f));
            }
            *(float4*)(a_s + r * 36 + kk) = o;
        }
#pragma unroll
        for (int i = t; i < 512; i += 256) {
            int kl = i >> 4, n4 = (i & 15) << 2;
            float4 v = *(const float4*)(W + (kc + kl) * 64 + n4);
            float4 o;
            o.x = f2tf(v.x); o.y = f2tf(v.y); o.z = f2tf(v.z); o.w = f2tf(v.w);
            *(float4*)(w_s + kl * 68 + n4) = o;
        }
        __syncthreads();
#pragma unroll
        for (int kk = 0; kk < 32; kk += 8) {
            int n = n0w + g;
            unsigned b0 = __float_as_uint(w_s[(kk + q) * 68 + n]);
            unsigned b1 = __float_as_uint(w_s[(kk + 4 + q) * 68 + n]);
#pragma unroll
            for (int mt = 0; mt < 8; mt++) {
                int r = mt * 16 + g;
                unsigned a0 = __float_as_uint(a_s[r * 36 + kk + q]);
                unsigned a1 = __float_as_uint(a_s[(r + 8) * 36 + kk + q]);
                unsigned a2 = __float_as_uint(a_s[r * 36 + kk + 4 + q]);
                unsigned a3 = __float_as_uint(a_s[(r + 8) * 36 + kk + 4 + q]);
                mma_tf32(acc[mt], a0, a1, a2, a3, b0, b1);
            }
        }
        __syncthreads();
    }
    int c = n0w + 2 * q;
    float2 bv = *(const float2*)(bias + c);
#pragma unroll
    for (int mt = 0; mt < 8; mt++) {
        int rA = row0 + mt * 16 + g, rB = rA + 8;
        if (rA < NN) {
            float2 hv = *(float2*)(g_h + (size_t)rA * 64 + c);
            hv.x += acc[mt][0] + bv.x;
            hv.y += acc[mt][1] + bv.y;
            *(float2*)(g_h + (size_t)rA * 64 + c) = hv;
            *(__half2*)(g_hmsg + (size_t)rA * 64 + c) =
                __floats2half2_rn(fmaxf(hv.x, 0.f) + EPS_MSG, fmaxf(hv.y, 0.f) + EPS_MSG);
        }
        if (rB < NN) {
            float2 hv = *(float2*)(g_h + (size_t)rB * 64 + c);
            hv.x += acc[mt][2] + bv.x;
            hv.y += acc[mt][3] + bv.y;
            *(float2*)(g_h + (size_t)rB * 64 + c) = hv;
            *(__half2*)(g_hmsg + (size_t)rB * 64 + c) =
                __floats2half2_rn(fmaxf(hv.x, 0.f) + EPS_MSG, fmaxf(hv.y, 0.f) + EPS_MSG);
        }
    }
}

// ---------------- pool: run-length max over sorted batch + encoded atomicMax ----------------
__global__ void __launch_bounds__(256) k_pool(const int* __restrict__ batch) {
    int t = threadIdx.x;
    int c = t & 63, sub = t >> 6;
    int n0 = blockIdx.x * 64 + sub * 16;
    float cur = -__int_as_float(0x7f800000);  // -inf
    int curb = -1;
    for (int i = 0; i < 16; i++) {
        int n = n0 + i;
        if (n >= NN) break;
        int b = batch[n];
        if (b != curb) {
            if (curb >= 0) atomicMax(&g_pool[curb * 64 + c], encf(cur));
            curb = b;
            cur = -__int_as_float(0x7f800000);
        }
        cur = fmaxf(cur, g_h[n * 64 + c]);
    }
    if (curb >= 0) atomicMax(&g_pool[curb * 64 + c], encf(cur));
}

// ---------------- final MLP: [64,64] -> relu -> [64,80] ----------------
__global__ void __launch_bounds__(256) k_final(const float* __restrict__ w1,
                                               const float* __restrict__ b1,
                                               const float* __restrict__ w2,
                                               const float* __restrict__ b2,
                                               float* __restrict__ out) {
    __shared__ float g_s[64 * 64];
    __shared__ float t_s[64 * 64];
    int t = threadIdx.x;
    for (int i = t; i < 4096; i += 256) {
        unsigned u = g_pool[i];
        g_s[i] = (u == ENC_NEGINF) ? 0.f : decf(u);
    }
    __syncthreads();
    for (int e = t; e < 4096; e += 256) {
        int r = e >> 6, c = e & 63;
        float a = b1[c];
        for (int k = 0; k < 64; k++) a = fmaf(g_s[r * 64 + k], w1[k * 64 + c], a);
        t_s[e] = fmaxf(a, 0.f);
    }
    __syncthreads();
    for (int e = t; e < 5120; e += 256) {
        int r = e / 80, c = e % 80;
        float a = b2[c];
        for (int k = 0; k < 64; k++) a = fmaf(t_s[r * 64 + k], w2[k * 80 + c], a);
        out[e] = a;
    }
}

// ---------------- launch ----------------
extern "C" void kernel_launch(void* const* d_in, const int* in_sizes, int n_in,
                              void* d_out, int out_size) {
    const float* x    = (const float*)d_in[0];
    const int*   ei   = (const int*)d_in[1];
    const int*   batch = (const int*)d_in[2];
    const float* cw1  = (const float*)d_in[3];
    const float* cb1  = (const float*)d_in[4];
    const float* cg1  = (const float*)d_in[5];
    const float* cbe1 = (const float*)d_in[6];
    const float* cw2  = (const float*)d_in[7];
    const float* cb2  = (const float*)d_in[8];
    const float* Lw1  = (const float*)d_in[9];
    const float* Lb1  = (const float*)d_in[10];
    const float* Lg1  = (const float*)d_in[11];
    const float* Lbe1 = (const float*)d_in[12];
    const float* Lw2  = (const float*)d_in[13];
    const float* Lb2  = (const float*)d_in[14];
    const float* mw1  = (const float*)d_in[15];
    const float* mb1  = (const float*)d_in[16];
    const float* mw2  = (const float*)d_in[17];
    const float* mb2  = (const float*)d_in[18];
    float* out = (float*)d_out;

    const int* src = ei;
    const int* dst = ei + EE;

    // CSR build
    k_init<<<391, 256>>>(x);
    k_deg<<<EE / 256, 256>>>(dst);
    k_scan1<<<98, 1024>>>();
    k_scan3<<<391, 256>>>();
    k_scatter<<<EE / 256, 256>>>(src, dst);

    // layer 0 (6 -> 12 -> 64), h = relu(genconv(x))
    k_l0<<<391, 256>>>(x, cw1, cb1, cg1, cbe1);
    k_l0_mlp2<<<391, 256>>>(cw2, cb2);

    // layers 1..3: h += genconv(relu(h))
    for (int i = 0; i < 3; i++) {
        k_agg64<<<12500, 256>>>();
        k_gemm1<<<782, 256>>>(Lw1 + i * 64 * 128, Lb1 + i * 128,
                              Lg1 + i * 128, Lbe1 + i * 128);
        k_gemm2<<<782, 256>>>(Lw2 + i * 128 * 64, Lb2 + i * 64);
    }

    k_pool<<<1563, 256>>>(batch);
    k_final<<<1, 256>>>(mw1, mb1, mw2, mb2, out);
}

// round 8
// speedup vs baseline: 1.2627x; 1.0945x over previous
#include <cuda_runtime.h>

#define NN 100000
#define EE 1600000
#define BB 64
#define EPS_MSG 1e-7f
#define ENC_NEGINF 0x007FFFFFu

// ---------------- scratch (static __device__, no allocations) ----------------
__device__ float  g_h[NN * 64];        // node state h (fp32)
__device__ float  g_out64[NN * 64];    // agg + residual (GEMM1 input)
__device__ float  g_hidden[NN * 128];  // MLP hidden (reused as [N,12] for layer 0)
__device__ float  g_x8[NN * 8];        // relu(x)+eps padded to 8 (layer-0 messages)
__device__ int    g_deg[NN];
__device__ int    g_tmp[NN];
__device__ int    g_rowptr[NN + 1];
__device__ int    g_pos[NN];
__device__ int    g_col[EE];
__device__ int    g_bsum[128];
__device__ float  g_psum[2048 * 128];
__device__ float  g_psumsq[2048 * 128];
__device__ float  g_scale[128];
__device__ float  g_shift[128];
__device__ unsigned g_pool[BB * 64];
__device__ int    g_ctr;   // last-block counter (reset by last block each use)

// ---------------- helpers ----------------
__device__ __forceinline__ unsigned encf(float f) {
    unsigned u = __float_as_uint(f);
    return (u & 0x80000000u) ? ~u : (u | 0x80000000u);
}
__device__ __forceinline__ float decf(unsigned u) {
    return __uint_as_float((u & 0x80000000u) ? (u ^ 0x80000000u) : ~u);
}
__device__ __forceinline__ float f2tf(float x) {
    unsigned r;
    asm("cvt.rna.tf32.f32 %0, %1;" : "=r"(r) : "f"(x));
    return __uint_as_float(r);
}
__device__ __forceinline__ void mma_tf32(float* d, unsigned a0, unsigned a1,
                                         unsigned a2, unsigned a3,
                                         unsigned b0, unsigned b1) {
    asm volatile(
        "mma.sync.aligned.m16n8k8.row.col.f32.tf32.tf32.f32 "
        "{%0,%1,%2,%3}, {%4,%5,%6,%7}, {%8,%9}, {%0,%1,%2,%3};"
        : "+f"(d[0]), "+f"(d[1]), "+f"(d[2]), "+f"(d[3])
        : "r"(a0), "r"(a1), "r"(a2), "r"(a3), "r"(b0), "r"(b1));
}

// per-float4 message accumulate: relu+eps, exp, p/q update (channels kx..kx+3)
#define ACC4(v, kx)                                                             \
    do {                                                                        \
        float a, ex;                                                            \
        a = fmaxf((v).x, 0.f) + EPS_MSG; ex = __expf(a);                        \
        p[(kx)] += ex;     q[(kx)] = fmaf(a, ex, q[(kx)]);                      \
        a = fmaxf((v).y, 0.f) + EPS_MSG; ex = __expf(a);                        \
        p[(kx) + 1] += ex; q[(kx) + 1] = fmaf(a, ex, q[(kx) + 1]);              \
        a = fmaxf((v).z, 0.f) + EPS_MSG; ex = __expf(a);                        \
        p[(kx) + 2] += ex; q[(kx) + 2] = fmaf(a, ex, q[(kx) + 2]);              \
        a = fmaxf((v).w, 0.f) + EPS_MSG; ex = __expf(a);                        \
        p[(kx) + 3] += ex; q[(kx) + 3] = fmaf(a, ex, q[(kx) + 3]);              \
    } while (0)

// ---------------- init: zero deg/pool, build padded layer-0 messages ----------------
__global__ void k_init(const float* __restrict__ x) {
    int i = blockIdx.x * blockDim.x + threadIdx.x;
    if (i < NN) {
        g_deg[i] = 0;
        float4 a, b;
        a.x = fmaxf(x[i * 6 + 0], 0.f) + EPS_MSG;
        a.y = fmaxf(x[i * 6 + 1], 0.f) + EPS_MSG;
        a.z = fmaxf(x[i * 6 + 2], 0.f) + EPS_MSG;
        a.w = fmaxf(x[i * 6 + 3], 0.f) + EPS_MSG;
        b.x = fmaxf(x[i * 6 + 4], 0.f) + EPS_MSG;
        b.y = fmaxf(x[i * 6 + 5], 0.f) + EPS_MSG;
        b.z = 0.f; b.w = 0.f;
        ((float4*)g_x8)[i * 2] = a;
        ((float4*)g_x8)[i * 2 + 1] = b;
    }
    if (i < BB * 64) g_pool[i] = ENC_NEGINF;
}

// ---------------- CSR build ----------------
__global__ void k_deg(const int* __restrict__ dst) {
    int e = blockIdx.x * blockDim.x + threadIdx.x;
    if (e < EE) atomicAdd(&g_deg[dst[e]], 1);
}

__global__ void __launch_bounds__(1024) k_scan1() {
    __shared__ int s[1024];
    int t = threadIdx.x;
    int idx = blockIdx.x * 1024 + t;
    int v = (idx < NN) ? g_deg[idx] : 0;
    s[t] = v;
    __syncthreads();
    for (int off = 1; off < 1024; off <<= 1) {
        int a = (t >= off) ? s[t - off] : 0;
        __syncthreads();
        s[t] += a;
        __syncthreads();
    }
    if (idx < NN) g_tmp[idx] = s[t];
    if (t == 1023) g_bsum[blockIdx.x] = s[1023];
}

// scan of 98 block sums fused into the apply pass
__global__ void k_scan3() {
    __shared__ int s[128];
    int t = threadIdx.x;
    if (t < 128) s[t] = (t < 98) ? g_bsum[t] : 0;
    __syncthreads();
    for (int off = 1; off < 128; off <<= 1) {
        int a = (t >= off && t < 128) ? s[t - off] : 0;
        __syncthreads();
        if (t < 128) s[t] += a;
        __syncthreads();
    }
    int idx = blockIdx.x * blockDim.x + t;
    if (idx >= NN) return;
    int b = idx >> 10;
    int off = (b > 0) ? s[b - 1] : 0;
    int incl = g_tmp[idx] + off;
    g_rowptr[idx + 1] = incl;
    g_pos[idx] = incl - g_deg[idx];
    if (idx == 0) g_rowptr[0] = 0;
}

__global__ void k_scatter(const int* __restrict__ src, const int* __restrict__ dst) {
    int e = blockIdx.x * blockDim.x + threadIdx.x;
    if (e >= EE) return;
    int p = atomicAdd(&g_pos[dst[e]], 1);
    g_col[p] = src[e];
}

// ---------------- layer 0: agg(F=6, shift-free softmax) + MLP1 (6->12) + BN ----------------
__global__ void __launch_bounds__(256) k_l0(const float* __restrict__ x,
                                            const float* __restrict__ w1,
                                            const float* __restrict__ b1,
                                            const float* __restrict__ gam,
                                            const float* __restrict__ bet) {
    __shared__ float w_s[72];
    __shared__ float sacc[12], sacc2[12];
    __shared__ int isLast;
    int t = threadIdx.x;
    if (t < 72) w_s[t] = w1[t];
    if (t < 12) { sacc[t] = 0.f; sacc2[t] = 0.f; }
    __syncthreads();

    int n = blockIdx.x * 256 + t;
    float hid[12];
#pragma unroll
    for (int j = 0; j < 12; j++) hid[j] = 0.f;

    if (n < NN) {
        int beg = g_rowptr[n], end = g_rowptr[n + 1];
        float p[6], q[6];
#pragma unroll
        for (int c = 0; c < 6; c++) { p[c] = 0.f; q[c] = 0.f; }
        const float4* __restrict__ X8 = (const float4*)g_x8;
        int e = beg;
        for (; e + 1 < end; e += 2) {  // 2-edge unroll -> 4 LDG.128 in flight
            int s0 = g_col[e], s1 = g_col[e + 1];
            float4 u0 = X8[s0 * 2], u1 = X8[s0 * 2 + 1];
            float4 w0 = X8[s1 * 2], w1v = X8[s1 * 2 + 1];
            float ex;
            ex = __expf(u0.x); p[0] += ex; q[0] = fmaf(u0.x, ex, q[0]);
            ex = __expf(u0.y); p[1] += ex; q[1] = fmaf(u0.y, ex, q[1]);
            ex = __expf(u0.z); p[2] += ex; q[2] = fmaf(u0.z, ex, q[2]);
            ex = __expf(u0.w); p[3] += ex; q[3] = fmaf(u0.w, ex, q[3]);
            ex = __expf(u1.x); p[4] += ex; q[4] = fmaf(u1.x, ex, q[4]);
            ex = __expf(u1.y); p[5] += ex; q[5] = fmaf(u1.y, ex, q[5]);
            ex = __expf(w0.x); p[0] += ex; q[0] = fmaf(w0.x, ex, q[0]);
            ex = __expf(w0.y); p[1] += ex; q[1] = fmaf(w0.y, ex, q[1]);
            ex = __expf(w0.z); p[2] += ex; q[2] = fmaf(w0.z, ex, q[2]);
            ex = __expf(w0.w); p[3] += ex; q[3] = fmaf(w0.w, ex, q[3]);
            ex = __expf(w1v.x); p[4] += ex; q[4] = fmaf(w1v.x, ex, q[4]);
            ex = __expf(w1v.y); p[5] += ex; q[5] = fmaf(w1v.y, ex, q[5]);
        }
        for (; e < end; e++) {
            int s = g_col[e];
            float4 v0 = X8[s * 2];
            float4 v1 = X8[s * 2 + 1];
            float ex;
            ex = __expf(v0.x); p[0] += ex; q[0] = fmaf(v0.x, ex, q[0]);
            ex = __expf(v0.y); p[1] += ex; q[1] = fmaf(v0.y, ex, q[1]);
            ex = __expf(v0.z); p[2] += ex; q[2] = fmaf(v0.z, ex, q[2]);
            ex = __expf(v0.w); p[3] += ex; q[3] = fmaf(v0.w, ex, q[3]);
            ex = __expf(v1.x); p[4] += ex; q[4] = fmaf(v1.x, ex, q[4]);
            ex = __expf(v1.y); p[5] += ex; q[5] = fmaf(v1.y, ex, q[5]);
        }
        float o[6];
#pragma unroll
        for (int c = 0; c < 6; c++) o[c] = q[c] / (p[c] + 1e-16f) + x[n * 6 + c];
#pragma unroll
        for (int j = 0; j < 12; j++) {
            float a = b1[j];
#pragma unroll
            for (int c = 0; c < 6; c++) a = fmaf(o[c], w_s[c * 12 + j], a);
            hid[j] = a;
            g_hidden[n * 12 + j] = a;
        }
    }
#pragma unroll
    for (int j = 0; j < 12; j++) {
        float v = hid[j], v2 = v * v;
        for (int off = 16; off; off >>= 1) {
            v += __shfl_down_sync(0xffffffffu, v, off);
            v2 += __shfl_down_sync(0xffffffffu, v2, off);
        }
        if ((t & 31) == 0) { atomicAdd(&sacc[j], v); atomicAdd(&sacc2[j], v2); }
    }
    __syncthreads();
    if (t < 12) {
        g_psum[blockIdx.x * 12 + t] = sacc[t];
        g_psumsq[blockIdx.x * 12 + t] = sacc2[t];
    }
    __threadfence();
    if (t == 0) isLast = (atomicAdd(&g_ctr, 1) == (int)gridDim.x - 1);
    __syncthreads();
    if (isLast) {
        if (t == 0) g_ctr = 0;
        if (t < 12) {
            float s = 0.f, s2 = 0.f;
            for (int i = 0; i < (int)gridDim.x; i++) {
                s += g_psum[i * 12 + t];
                s2 += g_psumsq[i * 12 + t];
            }
            float mu = s / (float)NN;
            float var = fmaxf(s2 / (float)NN - mu * mu, 0.f);
            float sc = gam[t] * rsqrtf(var + 1e-5f);
            g_scale[t] = sc;
            g_shift[t] = bet[t] - mu * sc;
        }
    }
}

// ---------------- layer 0 MLP2: relu(bn(hid12)) @ w2[12,64] + b2 -> h = relu(.) ----------------
__global__ void __launch_bounds__(256) k_l0_mlp2(const float* __restrict__ w2,
                                                 const float* __restrict__ b2) {
    __shared__ float w_s[12 * 64];
    __shared__ float b_s[64];
    int t = threadIdx.x;
    for (int i = t; i < 768; i += 256) w_s[i] = w2[i];
    if (t < 64) b_s[t] = b2[t];
    __syncthreads();
    int n = blockIdx.x * 256 + t;
    if (n >= NN) return;
    float v[12];
#pragma unroll
    for (int j = 0; j < 12; j++)
        v[j] = fmaxf(fmaf(g_hidden[n * 12 + j], g_scale[j], g_shift[j]), 0.f);
    for (int c0 = 0; c0 < 64; c0 += 4) {
        float a0 = b_s[c0], a1 = b_s[c0 + 1], a2 = b_s[c0 + 2], a3 = b_s[c0 + 3];
#pragma unroll
        for (int j = 0; j < 12; j++) {
            float vj = v[j];
            a0 = fmaf(vj, w_s[j * 64 + c0], a0);
            a1 = fmaf(vj, w_s[j * 64 + c0 + 1], a1);
            a2 = fmaf(vj, w_s[j * 64 + c0 + 2], a2);
            a3 = fmaf(vj, w_s[j * 64 + c0 + 3], a3);
        }
        float4 o;
        o.x = fmaxf(a0, 0.f); o.y = fmaxf(a1, 0.f);
        o.z = fmaxf(a2, 0.f); o.w = fmaxf(a3, 0.f);
        *(float4*)(g_h + n * 64 + c0) = o;
    }
}

// ---------------- aggregation, F=64: warp/node, single-pass, 4-edge unroll ------------
// half-warp per edge (lanes 0-15 even edges, 16-31 odd); lane owns 4 channels.
// 4 independent LDG.128 per lane batched before use -> high MLP.
__global__ void __launch_bounds__(256) k_agg64() {
    int gt = blockIdx.x * blockDim.x + threadIdx.x;
    int n = gt >> 5;
    if (n >= NN) return;
    int lane = gt & 31;
    int half = lane >> 4, li = lane & 15;
    int beg = g_rowptr[n], end = g_rowptr[n + 1];
    const float4* __restrict__ H = (const float4*)g_h;

    float p[4], q[4];
#pragma unroll
    for (int k = 0; k < 4; k++) { p[k] = 0.f; q[k] = 0.f; }

    int e = beg + half;
    for (; e + 6 < end; e += 8) {  // 4 edges per half per iter
        int i0 = g_col[e], i1 = g_col[e + 2], i2 = g_col[e + 4], i3 = g_col[e + 6];
        float4 v0 = H[(size_t)i0 * 16 + li];
        float4 v1 = H[(size_t)i1 * 16 + li];
        float4 v2 = H[(size_t)i2 * 16 + li];
        float4 v3 = H[(size_t)i3 * 16 + li];
        ACC4(v0, 0);
        ACC4(v1, 0);
        ACC4(v2, 0);
        ACC4(v3, 0);
    }
    for (; e < end; e += 2) {
        int i0 = g_col[e];
        float4 v0 = H[(size_t)i0 * 16 + li];
        ACC4(v0, 0);
    }
    // merge halves (same channels, disjoint edges)
#pragma unroll
    for (int k = 0; k < 4; k++) {
        p[k] += __shfl_xor_sync(0xffffffffu, p[k], 16);
        q[k] += __shfl_xor_sync(0xffffffffu, q[k], 16);
    }
    if (half == 0) {
        float4 r = H[(size_t)n * 16 + li];
        float4 o;
        o.x = q[0] / (p[0] + 1e-16f) + fmaxf(r.x, 0.f);
        o.y = q[1] / (p[1] + 1e-16f) + fmaxf(r.y, 0.f);
        o.z = q[2] / (p[2] + 1e-16f) + fmaxf(r.z, 0.f);
        o.w = q[3] / (p[3] + 1e-16f) + fmaxf(r.w, 0.f);
        ((float4*)g_out64)[(size_t)n * 16 + li] = o;
    }
}

// ---------------- GEMM1 (tf32 mma): g_out64[N,64] @ W[64,128] + b -> g_hidden[N,128]
// Fused BN partial stats + last-block finalize.
__global__ void __launch_bounds__(256) k_gemm1(const float* __restrict__ W,
                                               const float* __restrict__ bias,
                                               const float* __restrict__ gam,
                                               const float* __restrict__ bet) {
    __shared__ float a_s[128 * 36];   // [row][k] stride 36
    __shared__ float w_s[32 * 132];   // [k][n] stride 132
    __shared__ int isLast;
    int t = threadIdx.x, lane = t & 31, warp = t >> 5;
    int q = lane & 3, g = lane >> 2;
    int row0 = blockIdx.x * 128;
    int n0w = warp * 16;
    float acc[8][2][4];
#pragma unroll
    for (int i = 0; i < 8; i++)
#pragma unroll
        for (int j = 0; j < 2; j++)
#pragma unroll
            for (int k = 0; k < 4; k++) acc[i][j][k] = 0.f;

    for (int kc = 0; kc < 64; kc += 32) {
#pragma unroll
        for (int i = t; i < 1024; i += 256) {
            int r = i >> 3, kk = (i & 7) << 2;
            int row = row0 + r;
            float4 v = make_float4(0.f, 0.f, 0.f, 0.f);
            if (row < NN) v = *(const float4*)(g_out64 + row * 64 + kc + kk);
            float4 o;
            o.x = f2tf(v.x); o.y = f2tf(v.y); o.z = f2tf(v.z); o.w = f2tf(v.w);
            *(float4*)(a_s + r * 36 + kk) = o;
        }
#pragma unroll
        for (int i = t; i < 1024; i += 256) {
            int kl = i >> 5, n4 = (i & 31) << 2;
            float4 v = *(const float4*)(W + (kc + kl) * 128 + n4);
            float4 o;
            o.x = f2tf(v.x); o.y = f2tf(v.y); o.z = f2tf(v.z); o.w = f2tf(v.w);
            *(float4*)(w_s + kl * 132 + n4) = o;
        }
        __syncthreads();
#pragma unroll
        for (int kk = 0; kk < 32; kk += 8) {
            unsigned b[2][2];
#pragma unroll
            for (int nt = 0; nt < 2; nt++) {
                int n = n0w + nt * 8 + g;
                b[nt][0] = __float_as_uint(w_s[(kk + q) * 132 + n]);
                b[nt][1] = __float_as_uint(w_s[(kk + 4 + q) * 132 + n]);
            }
#pragma unroll
            for (int mt = 0; mt < 8; mt++) {
                int r = mt * 16 + g;
                unsigned a0 = __float_as_uint(a_s[r * 36 + kk + q]);
                unsigned a1 = __float_as_uint(a_s[(r + 8) * 36 + kk + q]);
                unsigned a2 = __float_as_uint(a_s[r * 36 + kk + 4 + q]);
                unsigned a3 = __float_as_uint(a_s[(r + 8) * 36 + kk + 4 + q]);
                mma_tf32(acc[mt][0], a0, a1, a2, a3, b[0][0], b[0][1]);
                mma_tf32(acc[mt][1], a0, a1, a2, a3, b[1][0], b[1][1]);
            }
        }
        __syncthreads();
    }
#pragma unroll
    for (int nt = 0; nt < 2; nt++) {
        int c = n0w + nt * 8 + 2 * q;
        float2 bv = *(const float2*)(bias + c);
        float s0 = 0.f, s1 = 0.f, s20 = 0.f, s21 = 0.f;
#pragma unroll
        for (int mt = 0; mt < 8; mt++) {
            int rA = row0 + mt * 16 + g, rB = rA + 8;
            float v0 = acc[mt][nt][0] + bv.x, v1 = acc[mt][nt][1] + bv.y;
            float v2 = acc[mt][nt][2] + bv.x, v3 = acc[mt][nt][3] + bv.y;
            if (rA < NN) {
                *(float2*)(g_hidden + (size_t)rA * 128 + c) = make_float2(v0, v1);
                s0 += v0; s20 = fmaf(v0, v0, s20);
                s1 += v1; s21 = fmaf(v1, v1, s21);
            }
            if (rB < NN) {
                *(float2*)(g_hidden + (size_t)rB * 128 + c) = make_float2(v2, v3);
                s0 += v2; s20 = fmaf(v2, v2, s20);
                s1 += v3; s21 = fmaf(v3, v3, s21);
            }
        }
#pragma unroll
        for (int off = 16; off >= 4; off >>= 1) {
            s0 += __shfl_down_sync(0xffffffffu, s0, off);
            s1 += __shfl_down_sync(0xffffffffu, s1, off);
            s20 += __shfl_down_sync(0xffffffffu, s20, off);
            s21 += __shfl_down_sync(0xffffffffu, s21, off);
        }
        if (lane < 4) {
            int cc = n0w + nt * 8 + 2 * lane;
            g_psum[blockIdx.x * 128 + cc] = s0;
            g_psum[blockIdx.x * 128 + cc + 1] = s1;
            g_psumsq[blockIdx.x * 128 + cc] = s20;
            g_psumsq[blockIdx.x * 128 + cc + 1] = s21;
        }
    }
    __threadfence();
    if (t == 0) isLast = (atomicAdd(&g_ctr, 1) == (int)gridDim.x - 1);
    __syncthreads();
    if (isLast) {
        if (t == 0) g_ctr = 0;
        if (t < 128) {
            float s = 0.f, s2 = 0.f;
            int nb = (int)gridDim.x;
#pragma unroll 4
            for (int i = 0; i < nb; i++) {
                s += g_psum[i * 128 + t];
                s2 += g_psumsq[i * 128 + t];
            }
            float mu = s / (float)NN;
            float var = fmaxf(s2 / (float)NN - mu * mu, 0.f);
            float sc = gam[t] * rsqrtf(var + 1e-5f);
            g_scale[t] = sc;
            g_shift[t] = bet[t] - mu * sc;
        }
    }
}

// ---------------- GEMM2 (tf32 mma): relu(bn(g_hidden))[N,128] @ W[128,64] + b; h += .
__global__ void __launch_bounds__(256) k_gemm2(const float* __restrict__ W,
                                               const float* __restrict__ bias) {
    __shared__ float a_s[128 * 36];   // [row][k] stride 36
    __shared__ float w_s[32 * 68];    // [k][n] stride 68
    int t = threadIdx.x, lane = t & 31, warp = t >> 5;
    int q = lane & 3, g = lane >> 2;
    int row0 = blockIdx.x * 128;
    int n0w = warp * 8;
    float acc[8][4];
#pragma unroll
    for (int i = 0; i < 8; i++)
#pragma unroll
        for (int k = 0; k < 4; k++) acc[i][k] = 0.f;

    for (int kc = 0; kc < 128; kc += 32) {
#pragma unroll
        for (int i = t; i < 1024; i += 256) {
            int r = i >> 3, kk = (i & 7) << 2;
            int row = row0 + r;
            float4 o = make_float4(0.f, 0.f, 0.f, 0.f);
            if (row < NN) {
                float4 hv = *(const float4*)(g_hidden + (size_t)row * 128 + kc + kk);
                float4 sc = *(const float4*)(g_scale + kc + kk);
                float4 sh = *(const float4*)(g_shift + kc + kk);
                o.x = f2tf(fmaxf(fmaf(hv.x, sc.x, sh.x), 0.f));
                o.y = f2tf(fmaxf(fmaf(hv.y, sc.y, sh.y), 0.f));
                o.z = f2tf(fmaxf(fmaf(hv.z, sc.z, sh.z), 0.f));
                o.w = f2tf(fmaxf(fmaf(hv.w, sc.w, sh.w), 0.f));
            }
            *(float4*)(a_s + r * 36 + kk) = o;
        }
#pragma unroll
        for (int i = t; i < 512; i += 256) {
            int kl = i >> 4, n4 = (i & 15) << 2;
            float4 v = *(const float4*)(W + (kc + kl) * 64 + n4);
            float4 o;
            o.x = f2tf(v.x); o.y = f2tf(v.y); o.z = f2tf(v.z); o.w = f2tf(v.w);
            *(float4*)(w_s + kl * 68 + n4) = o;
        }
        __syncthreads();
#pragma unroll
        for (int kk = 0; kk < 32; kk += 8) {
            int n = n0w + g;
            unsigned b0 = __float_as_uint(w_s[(kk + q) * 68 + n]);
            unsigned b1 = __float_as_uint(w_s[(kk + 4 + q) * 68 + n]);
#pragma unroll
            for (int mt = 0; mt < 8; mt++) {
                int r = mt * 16 + g;
                unsigned a0 = __float_as_uint(a_s[r * 36 + kk + q]);
                unsigned a1 = __float_as_uint(a_s[(r + 8) * 36 + kk + q]);
                unsigned a2 = __float_as_uint(a_s[r * 36 + kk + 4 + q]);
                unsigned a3 = __float_as_uint(a_s[(r + 8) * 36 + kk + 4 + q]);
                mma_tf32(acc[mt], a0, a1, a2, a3, b0, b1);
            }
        }
        __syncthreads();
    }
    int c = n0w + 2 * q;
    float2 bv = *(const float2*)(bias + c);
#pragma unroll
    for (int mt = 0; mt < 8; mt++) {
        int rA = row0 + mt * 16 + g, rB = rA + 8;
        if (rA < NN) {
            float2 hv = *(float2*)(g_h + (size_t)rA * 64 + c);
            hv.x += acc[mt][0] + bv.x;
            hv.y += acc[mt][1] + bv.y;
            *(float2*)(g_h + (size_t)rA * 64 + c) = hv;
        }
        if (rB < NN) {
            float2 hv = *(float2*)(g_h + (size_t)rB * 64 + c);
            hv.x += acc[mt][2] + bv.x;
            hv.y += acc[mt][3] + bv.y;
            *(float2*)(g_h + (size_t)rB * 64 + c) = hv;
        }
    }
}

// ---------------- pool: run-length max over sorted batch + encoded atomicMax ----------------
__global__ void __launch_bounds__(256) k_pool(const int* __restrict__ batch) {
    int t = threadIdx.x;
    int c = t & 63, sub = t >> 6;
    int n0 = blockIdx.x * 64 + sub * 16;
    float cur = -__int_as_float(0x7f800000);  // -inf
    int curb = -1;
    for (int i = 0; i < 16; i++) {
        int n = n0 + i;
        if (n >= NN) break;
        int b = batch[n];
        if (b != curb) {
            if (curb >= 0) atomicMax(&g_pool[curb * 64 + c], encf(cur));
            curb = b;
            cur = -__int_as_float(0x7f800000);
        }
        cur = fmaxf(cur, g_h[n * 64 + c]);
    }
    if (curb >= 0) atomicMax(&g_pool[curb * 64 + c], encf(cur));
}

// ---------------- final MLP: [64,64] -> relu -> [64,80] ----------------
__global__ void __launch_bounds__(256) k_final(const float* __restrict__ w1,
                                               const float* __restrict__ b1,
                                               const float* __restrict__ w2,
                                               const float* __restrict__ b2,
                                               float* __restrict__ out) {
    __shared__ float g_s[64 * 64];
    __shared__ float t_s[64 * 64];
    int t = threadIdx.x;
    for (int i = t; i < 4096; i += 256) {
        unsigned u = g_pool[i];
        g_s[i] = (u == ENC_NEGINF) ? 0.f : decf(u);
    }
    __syncthreads();
    for (int e = t; e < 4096; e += 256) {
        int r = e >> 6, c = e & 63;
        float a = b1[c];
        for (int k = 0; k < 64; k++) a = fmaf(g_s[r * 64 + k], w1[k * 64 + c], a);
        t_s[e] = fmaxf(a, 0.f);
    }
    __syncthreads();
    for (int e = t; e < 5120; e += 256) {
        int r = e / 80, c = e % 80;
        float a = b2[c];
        for (int k = 0; k < 64; k++) a = fmaf(t_s[r * 64 + k], w2[k * 80 + c], a);
        out[e] = a;
    }
}

// ---------------- launch ----------------
extern "C" void kernel_launch(void* const* d_in, const int* in_sizes, int n_in,
                              void* d_out, int out_size) {
    const float* x    = (const float*)d_in[0];
    const int*   ei   = (const int*)d_in[1];
    const int*   batch = (const int*)d_in[2];
    const float* cw1  = (const float*)d_in[3];
    const float* cb1  = (const float*)d_in[4];
    const float* cg1  = (const float*)d_in[5];
    const float* cbe1 = (const float*)d_in[6];
    const float* cw2  = (const float*)d_in[7];
    const float* cb2  = (const float*)d_in[8];
    const float* Lw1  = (const float*)d_in[9];
    const float* Lb1  = (const float*)d_in[10];
    const float* Lg1  = (const float*)d_in[11];
    const float* Lbe1 = (const float*)d_in[12];
    const float* Lw2  = (const float*)d_in[13];
    const float* Lb2  = (const float*)d_in[14];
    const float* mw1  = (const float*)d_in[15];
    const float* mb1  = (const float*)d_in[16];
    const float* mw2  = (const float*)d_in[17];
    const float* mb2  = (const float*)d_in[18];
    float* out = (float*)d_out;

    const int* src = ei;
    const int* dst = ei + EE;

    // CSR build
    k_init<<<391, 256>>>(x);
    k_deg<<<EE / 256, 256>>>(dst);
    k_scan1<<<98, 1024>>>();
    k_scan3<<<391, 256>>>();
    k_scatter<<<EE / 256, 256>>>(src, dst);

    // layer 0 (6 -> 12 -> 64), h = relu(genconv(x))
    k_l0<<<391, 256>>>(x, cw1, cb1, cg1, cbe1);
    k_l0_mlp2<<<391, 256>>>(cw2, cb2);

    // layers 1..3: h += genconv(relu(h))
    for (int i = 0; i < 3; i++) {
        k_agg64<<<12500, 256>>>();
        k_gemm1<<<782, 256>>>(Lw1 + i * 64 * 128, Lb1 + i * 128,
                              Lg1 + i * 128, Lbe1 + i * 128);
        k_gemm2<<<782, 256>>>(Lw2 + i * 128 * 64, Lb2 + i * 64);
    }

    k_pool<<<1563, 256>>>(batch);
    k_final<<<1, 256>>>(mw1, mb1, mw2, mb2, out);
}

// round 9
// speedup vs baseline: 1.3504x; 1.0695x over previous
#include <cuda_runtime.h>
#include <cuda_fp16.h>

#define NN 100000
#define EE 1600000
#define BB 64
#define EPS_MSG 1e-7f

// ---------------- scratch (static __device__, no allocations) ----------------
__device__ float  g_h[NN * 64];        // node state h (fp32)
__device__ float  g_out64[NN * 64];    // agg + residual (GEMM1 input)
__device__ float  g_hidden[NN * 128];  // MLP hidden (reused as [N,12] for layer 0)
__device__ float  g_x8[NN * 8];        // relu(x)+eps padded to 8 (layer-0 messages)
__device__ int    g_deg[NN];           // zero at start; self-cleaned by k_scan3
__device__ int    g_tmp[NN];
__device__ int    g_rowptr[NN + 1];
__device__ int    g_pos[NN];
__device__ int    g_col[EE];
__device__ int    g_bsum[128];
__device__ float  g_psum[2048 * 128];
__device__ float  g_psumsq[2048 * 128];
__device__ float  g_scale[128];
__device__ float  g_shift[128];
__device__ unsigned g_pool[BB * 64];   // zero = empty; self-cleaned by k_final
__device__ int    g_ctr;               // last-block counter (self-cleaning)

// ---------------- helpers ----------------
// order-preserving float->uint encoding; never returns 0 for a real float
__device__ __forceinline__ unsigned encf(float f) {
    unsigned u = __float_as_uint(f);
    return (u & 0x80000000u) ? ~u : (u | 0x80000000u);
}
__device__ __forceinline__ float decf(unsigned u) {
    return __uint_as_float((u & 0x80000000u) ? (u ^ 0x80000000u) : ~u);
}
__device__ __forceinline__ void mma_f16(float* d, unsigned a0, unsigned a1,
                                        unsigned a2, unsigned a3,
                                        unsigned b0, unsigned b1) {
    asm volatile(
        "mma.sync.aligned.m16n8k16.row.col.f32.f16.f16.f32 "
        "{%0,%1,%2,%3}, {%4,%5,%6,%7}, {%8,%9}, {%0,%1,%2,%3};"
        : "+f"(d[0]), "+f"(d[1]), "+f"(d[2]), "+f"(d[3])
        : "r"(a0), "r"(a1), "r"(a2), "r"(a3), "r"(b0), "r"(b1));
}
__device__ __forceinline__ unsigned pack_h2(float a, float b) {
    __half2 h = __floats2half2_rn(a, b);
    return *(unsigned*)&h;
}

// per-float4 message accumulate: relu+eps, exp, p/q update (channels kx..kx+3)
#define ACC4(v, kx)                                                             \
    do {                                                                        \
        float a, ex;                                                            \
        a = fmaxf((v).x, 0.f) + EPS_MSG; ex = __expf(a);                        \
        p[(kx)] += ex;     q[(kx)] = fmaf(a, ex, q[(kx)]);                      \
        a = fmaxf((v).y, 0.f) + EPS_MSG; ex = __expf(a);                        \
        p[(kx) + 1] += ex; q[(kx) + 1] = fmaf(a, ex, q[(kx) + 1]);              \
        a = fmaxf((v).z, 0.f) + EPS_MSG; ex = __expf(a);                        \
        p[(kx) + 2] += ex; q[(kx) + 2] = fmaf(a, ex, q[(kx) + 2]);              \
        a = fmaxf((v).w, 0.f) + EPS_MSG; ex = __expf(a);                        \
        p[(kx) + 3] += ex; q[(kx) + 3] = fmaf(a, ex, q[(kx) + 3]);              \
    } while (0)

// ---------------- CSR: degree count + layer-0 message build ----------------
__global__ void k_deg(const int* __restrict__ dst, const float* __restrict__ x) {
    int e = blockIdx.x * blockDim.x + threadIdx.x;
    if (e < EE) atomicAdd(&g_deg[dst[e]], 1);
    if (e < NN) {
        float4 a, b;
        a.x = fmaxf(x[e * 6 + 0], 0.f) + EPS_MSG;
        a.y = fmaxf(x[e * 6 + 1], 0.f) + EPS_MSG;
        a.z = fmaxf(x[e * 6 + 2], 0.f) + EPS_MSG;
        a.w = fmaxf(x[e * 6 + 3], 0.f) + EPS_MSG;
        b.x = fmaxf(x[e * 6 + 4], 0.f) + EPS_MSG;
        b.y = fmaxf(x[e * 6 + 5], 0.f) + EPS_MSG;
        b.z = 0.f; b.w = 0.f;
        ((float4*)g_x8)[e * 2] = a;
        ((float4*)g_x8)[e * 2 + 1] = b;
    }
}

__global__ void __launch_bounds__(1024) k_scan1() {
    __shared__ int s[1024];
    int t = threadIdx.x;
    int idx = blockIdx.x * 1024 + t;
    int v = (idx < NN) ? g_deg[idx] : 0;
    s[t] = v;
    __syncthreads();
    for (int off = 1; off < 1024; off <<= 1) {
        int a = (t >= off) ? s[t - off] : 0;
        __syncthreads();
        s[t] += a;
        __syncthreads();
    }
    if (idx < NN) g_tmp[idx] = s[t];
    if (t == 1023) g_bsum[blockIdx.x] = s[1023];
}

// scan of 98 block sums fused into apply; self-cleans g_deg for next replay
__global__ void k_scan3() {
    __shared__ int s[128];
    int t = threadIdx.x;
    if (t < 128) s[t] = (t < 98) ? g_bsum[t] : 0;
    __syncthreads();
    for (int off = 1; off < 128; off <<= 1) {
        int a = (t >= off && t < 128) ? s[t - off] : 0;
        __syncthreads();
        if (t < 128) s[t] += a;
        __syncthreads();
    }
    int idx = blockIdx.x * blockDim.x + t;
    if (idx >= NN) return;
    int b = idx >> 10;
    int off = (b > 0) ? s[b - 1] : 0;
    int incl = g_tmp[idx] + off;
    g_rowptr[idx + 1] = incl;
    g_pos[idx] = incl - g_deg[idx];
    g_deg[idx] = 0;               // self-clean for next replay
    if (idx == 0) g_rowptr[0] = 0;
}

__global__ void k_scatter(const int* __restrict__ src, const int* __restrict__ dst) {
    int e = blockIdx.x * blockDim.x + threadIdx.x;
    if (e >= EE) return;
    int p = atomicAdd(&g_pos[dst[e]], 1);
    g_col[p] = src[e];
}

// ---------------- layer 0: agg(F=6, shift-free softmax) + MLP1 (6->12) + BN ----------------
__global__ void __launch_bounds__(256) k_l0(const float* __restrict__ x,
                                            const float* __restrict__ w1,
                                            const float* __restrict__ b1,
                                            const float* __restrict__ gam,
                                            const float* __restrict__ bet) {
    __shared__ float w_s[72];
    __shared__ float sacc[12], sacc2[12];
    __shared__ int isLast;
    int t = threadIdx.x;
    if (t < 72) w_s[t] = w1[t];
    if (t < 12) { sacc[t] = 0.f; sacc2[t] = 0.f; }
    __syncthreads();

    int n = blockIdx.x * 256 + t;
    float hid[12];
#pragma unroll
    for (int j = 0; j < 12; j++) hid[j] = 0.f;

    if (n < NN) {
        int beg = g_rowptr[n], end = g_rowptr[n + 1];
        float p[6], q[6];
#pragma unroll
        for (int c = 0; c < 6; c++) { p[c] = 0.f; q[c] = 0.f; }
        const float4* __restrict__ X8 = (const float4*)g_x8;
        int e = beg;
        for (; e + 1 < end; e += 2) {
            int s0 = g_col[e], s1 = g_col[e + 1];
            float4 u0 = X8[s0 * 2], u1 = X8[s0 * 2 + 1];
            float4 w0 = X8[s1 * 2], w1v = X8[s1 * 2 + 1];
            float ex;
            ex = __expf(u0.x); p[0] += ex; q[0] = fmaf(u0.x, ex, q[0]);
            ex = __expf(u0.y); p[1] += ex; q[1] = fmaf(u0.y, ex, q[1]);
            ex = __expf(u0.z); p[2] += ex; q[2] = fmaf(u0.z, ex, q[2]);
            ex = __expf(u0.w); p[3] += ex; q[3] = fmaf(u0.w, ex, q[3]);
            ex = __expf(u1.x); p[4] += ex; q[4] = fmaf(u1.x, ex, q[4]);
            ex = __expf(u1.y); p[5] += ex; q[5] = fmaf(u1.y, ex, q[5]);
            ex = __expf(w0.x); p[0] += ex; q[0] = fmaf(w0.x, ex, q[0]);
            ex = __expf(w0.y); p[1] += ex; q[1] = fmaf(w0.y, ex, q[1]);
            ex = __expf(w0.z); p[2] += ex; q[2] = fmaf(w0.z, ex, q[2]);
            ex = __expf(w0.w); p[3] += ex; q[3] = fmaf(w0.w, ex, q[3]);
            ex = __expf(w1v.x); p[4] += ex; q[4] = fmaf(w1v.x, ex, q[4]);
            ex = __expf(w1v.y); p[5] += ex; q[5] = fmaf(w1v.y, ex, q[5]);
        }
        for (; e < end; e++) {
            int s = g_col[e];
            float4 v0 = X8[s * 2];
            float4 v1 = X8[s * 2 + 1];
            float ex;
            ex = __expf(v0.x); p[0] += ex; q[0] = fmaf(v0.x, ex, q[0]);
            ex = __expf(v0.y); p[1] += ex; q[1] = fmaf(v0.y, ex, q[1]);
            ex = __expf(v0.z); p[2] += ex; q[2] = fmaf(v0.z, ex, q[2]);
            ex = __expf(v0.w); p[3] += ex; q[3] = fmaf(v0.w, ex, q[3]);
            ex = __expf(v1.x); p[4] += ex; q[4] = fmaf(v1.x, ex, q[4]);
            ex = __expf(v1.y); p[5] += ex; q[5] = fmaf(v1.y, ex, q[5]);
        }
        float o[6];
#pragma unroll
        for (int c = 0; c < 6; c++) o[c] = q[c] / (p[c] + 1e-16f) + x[n * 6 + c];
#pragma unroll
        for (int j = 0; j < 12; j++) {
            float a = b1[j];
#pragma unroll
            for (int c = 0; c < 6; c++) a = fmaf(o[c], w_s[c * 12 + j], a);
            hid[j] = a;
            g_hidden[n * 12 + j] = a;
        }
    }
#pragma unroll
    for (int j = 0; j < 12; j++) {
        float v = hid[j], v2 = v * v;
        for (int off = 16; off; off >>= 1) {
            v += __shfl_down_sync(0xffffffffu, v, off);
            v2 += __shfl_down_sync(0xffffffffu, v2, off);
        }
        if ((t & 31) == 0) { atomicAdd(&sacc[j], v); atomicAdd(&sacc2[j], v2); }
    }
    __syncthreads();
    if (t < 12) {
        g_psum[blockIdx.x * 12 + t] = sacc[t];
        g_psumsq[blockIdx.x * 12 + t] = sacc2[t];
    }
    __threadfence();
    if (t == 0) isLast = (atomicAdd(&g_ctr, 1) == (int)gridDim.x - 1);
    __syncthreads();
    if (isLast) {
        if (t == 0) g_ctr = 0;
        if (t < 12) {
            float s = 0.f, s2 = 0.f;
            for (int i = 0; i < (int)gridDim.x; i++) {
                s += g_psum[i * 12 + t];
                s2 += g_psumsq[i * 12 + t];
            }
            float mu = s / (float)NN;
            float var = fmaxf(s2 / (float)NN - mu * mu, 0.f);
            float sc = gam[t] * rsqrtf(var + 1e-5f);
            g_scale[t] = sc;
            g_shift[t] = bet[t] - mu * sc;
        }
    }
}

// ---------------- layer 0 MLP2: relu(bn(hid12)) @ w2[12,64] + b2 -> h = relu(.) ----------------
__global__ void __launch_bounds__(256) k_l0_mlp2(const float* __restrict__ w2,
                                                 const float* __restrict__ b2) {
    __shared__ float w_s[12 * 64];
    __shared__ float b_s[64];
    int t = threadIdx.x;
    for (int i = t; i < 768; i += 256) w_s[i] = w2[i];
    if (t < 64) b_s[t] = b2[t];
    __syncthreads();
    int n = blockIdx.x * 256 + t;
    if (n >= NN) return;
    float v[12];
#pragma unroll
    for (int j = 0; j < 12; j++)
        v[j] = fmaxf(fmaf(g_hidden[n * 12 + j], g_scale[j], g_shift[j]), 0.f);
    for (int c0 = 0; c0 < 64; c0 += 4) {
        float a0 = b_s[c0], a1 = b_s[c0 + 1], a2 = b_s[c0 + 2], a3 = b_s[c0 + 3];
#pragma unroll
        for (int j = 0; j < 12; j++) {
            float vj = v[j];
            a0 = fmaf(vj, w_s[j * 64 + c0], a0);
            a1 = fmaf(vj, w_s[j * 64 + c0 + 1], a1);
            a2 = fmaf(vj, w_s[j * 64 + c0 + 2], a2);
            a3 = fmaf(vj, w_s[j * 64 + c0 + 3], a3);
        }
        float4 o;
        o.x = fmaxf(a0, 0.f); o.y = fmaxf(a1, 0.f);
        o.z = fmaxf(a2, 0.f); o.w = fmaxf(a3, 0.f);
        *(float4*)(g_h + n * 64 + c0) = o;
    }
}

// ---------------- aggregation, F=64: warp/node, single-pass (MUFU-bound floor) --------
__global__ void __launch_bounds__(256) k_agg64() {
    int gt = blockIdx.x * blockDim.x + threadIdx.x;
    int n = gt >> 5;
    if (n >= NN) return;
    int lane = gt & 31;
    int half = lane >> 4, li = lane & 15;
    int beg = g_rowptr[n], end = g_rowptr[n + 1];
    const float4* __restrict__ H = (const float4*)g_h;

    float p[4], q[4];
#pragma unroll
    for (int k = 0; k < 4; k++) { p[k] = 0.f; q[k] = 0.f; }

    int e = beg + half;
    for (; e + 2 < end; e += 4) {
        int i0 = g_col[e], i1 = g_col[e + 2];
        float4 v0 = H[(size_t)i0 * 16 + li];
        float4 v1 = H[(size_t)i1 * 16 + li];
        ACC4(v0, 0);
        ACC4(v1, 0);
    }
    for (; e < end; e += 2) {
        int i0 = g_col[e];
        float4 v0 = H[(size_t)i0 * 16 + li];
        ACC4(v0, 0);
    }
#pragma unroll
    for (int k = 0; k < 4; k++) {
        p[k] += __shfl_xor_sync(0xffffffffu, p[k], 16);
        q[k] += __shfl_xor_sync(0xffffffffu, q[k], 16);
    }
    if (half == 0) {
        float4 r = H[(size_t)n * 16 + li];
        float4 o;
        o.x = q[0] / (p[0] + 1e-16f) + fmaxf(r.x, 0.f);
        o.y = q[1] / (p[1] + 1e-16f) + fmaxf(r.y, 0.f);
        o.z = q[2] / (p[2] + 1e-16f) + fmaxf(r.z, 0.f);
        o.w = q[3] / (p[3] + 1e-16f) + fmaxf(r.w, 0.f);
        ((float4*)g_out64)[(size_t)n * 16 + li] = o;
    }
}

// ---------------- GEMM1 (fp16 m16n8k16): g_out64[N,64] @ W[64,128] + b -> g_hidden
// A staged as half [128][72]; W staged transposed as half [n=128][72].
// Fused BN partial stats + last-block finalize. Accumulate fp32.
__global__ void __launch_bounds__(256) k_gemm1(const float* __restrict__ W,
                                               const float* __restrict__ bias,
                                               const float* __restrict__ gam,
                                               const float* __restrict__ bet) {
    __shared__ __half a_s[128 * 72];
    __shared__ __half w_s[128 * 72];   // [n][k]
    __shared__ int isLast;
    int t = threadIdx.x, lane = t & 31, warp = t >> 5;
    int q = lane & 3, g = lane >> 2;
    int row0 = blockIdx.x * 128;
    int n0w = warp * 16;

    // stage A [128 rows][64 k] -> half
#pragma unroll
    for (int i = t; i < 2048; i += 256) {
        int r = i >> 4, kk = (i & 15) << 2;
        int row = row0 + r;
        float4 v = make_float4(0.f, 0.f, 0.f, 0.f);
        if (row < NN) v = *(const float4*)(g_out64 + (size_t)row * 64 + kk);
        uint2 u;
        u.x = pack_h2(v.x, v.y);
        u.y = pack_h2(v.z, v.w);
        *(uint2*)(a_s + r * 72 + kk) = u;
    }
    // stage W transposed: w_s[n][k] <- W[k][n]
#pragma unroll
    for (int i = t; i < 2048; i += 256) {
        int n = i & 127, kb = (i >> 7) << 2;
        float v0 = W[(kb + 0) * 128 + n];
        float v1 = W[(kb + 1) * 128 + n];
        float v2 = W[(kb + 2) * 128 + n];
        float v3 = W[(kb + 3) * 128 + n];
        uint2 u;
        u.x = pack_h2(v0, v1);
        u.y = pack_h2(v2, v3);
        *(uint2*)(w_s + n * 72 + kb) = u;
    }
    __syncthreads();

    float acc[8][2][4];
#pragma unroll
    for (int i = 0; i < 8; i++)
#pragma unroll
        for (int j = 0; j < 2; j++)
#pragma unroll
            for (int k = 0; k < 4; k++) acc[i][j][k] = 0.f;

#pragma unroll
    for (int ks = 0; ks < 64; ks += 16) {
        unsigned b[2][2];
#pragma unroll
        for (int nt = 0; nt < 2; nt++) {
            int n = n0w + nt * 8 + g;
            b[nt][0] = *(unsigned*)(w_s + n * 72 + ks + 2 * q);
            b[nt][1] = *(unsigned*)(w_s + n * 72 + ks + 2 * q + 8);
        }
#pragma unroll
        for (int mt = 0; mt < 8; mt++) {
            int r = mt * 16 + g;
            unsigned a0 = *(unsigned*)(a_s + r * 72 + ks + 2 * q);
            unsigned a1 = *(unsigned*)(a_s + (r + 8) * 72 + ks + 2 * q);
            unsigned a2 = *(unsigned*)(a_s + r * 72 + ks + 2 * q + 8);
            unsigned a3 = *(unsigned*)(a_s + (r + 8) * 72 + ks + 2 * q + 8);
            mma_f16(acc[mt][0], a0, a1, a2, a3, b[0][0], b[0][1]);
            mma_f16(acc[mt][1], a0, a1, a2, a3, b[1][0], b[1][1]);
        }
    }

    // epilogue: +bias, store, fused BN partial stats
#pragma unroll
    for (int nt = 0; nt < 2; nt++) {
        int c = n0w + nt * 8 + 2 * q;
        float2 bv = *(const float2*)(bias + c);
        float s0 = 0.f, s1 = 0.f, s20 = 0.f, s21 = 0.f;
#pragma unroll
        for (int mt = 0; mt < 8; mt++) {
            int rA = row0 + mt * 16 + g, rB = rA + 8;
            float v0 = acc[mt][nt][0] + bv.x, v1 = acc[mt][nt][1] + bv.y;
            float v2 = acc[mt][nt][2] + bv.x, v3 = acc[mt][nt][3] + bv.y;
            if (rA < NN) {
                *(float2*)(g_hidden + (size_t)rA * 128 + c) = make_float2(v0, v1);
                s0 += v0; s20 = fmaf(v0, v0, s20);
                s1 += v1; s21 = fmaf(v1, v1, s21);
            }
            if (rB < NN) {
                *(float2*)(g_hidden + (size_t)rB * 128 + c) = make_float2(v2, v3);
                s0 += v2; s20 = fmaf(v2, v2, s20);
                s1 += v3; s21 = fmaf(v3, v3, s21);
            }
        }
#pragma unroll
        for (int off = 16; off >= 4; off >>= 1) {
            s0 += __shfl_down_sync(0xffffffffu, s0, off);
            s1 += __shfl_down_sync(0xffffffffu, s1, off);
            s20 += __shfl_down_sync(0xffffffffu, s20, off);
            s21 += __shfl_down_sync(0xffffffffu, s21, off);
        }
        if (lane < 4) {
            int cc = n0w + nt * 8 + 2 * lane;
            g_psum[blockIdx.x * 128 + cc] = s0;
            g_psum[blockIdx.x * 128 + cc + 1] = s1;
            g_psumsq[blockIdx.x * 128 + cc] = s20;
            g_psumsq[blockIdx.x * 128 + cc + 1] = s21;
        }
    }
    __threadfence();
    if (t == 0) isLast = (atomicAdd(&g_ctr, 1) == (int)gridDim.x - 1);
    __syncthreads();
    if (isLast) {
        if (t == 0) g_ctr = 0;
        if (t < 128) {
            float s = 0.f, s2 = 0.f;
            int nb = (int)gridDim.x;
#pragma unroll 4
            for (int i = 0; i < nb; i++) {
                s += g_psum[i * 128 + t];
                s2 += g_psumsq[i * 128 + t];
            }
            float mu = s / (float)NN;
            float var = fmaxf(s2 / (float)NN - mu * mu, 0.f);
            float sc = gam[t] * rsqrtf(var + 1e-5f);
            g_scale[t] = sc;
            g_shift[t] = bet[t] - mu * sc;
        }
    }
}

// ---------------- GEMM2 (fp16 m16n8k16): relu(bn(g_hidden)) @ W[128,64] + b; h += .
__global__ void __launch_bounds__(256) k_gemm2(const float* __restrict__ W,
                                               const float* __restrict__ bias) {
    __shared__ __half a_s[128 * 72];
    __shared__ __half w_s[64 * 72];    // [n][k-chunk]
    int t = threadIdx.x, lane = t & 31, warp = t >> 5;
    int q = lane & 3, g = lane >> 2;
    int row0 = blockIdx.x * 128;
    int n0w = warp * 8;
    float acc[8][4];
#pragma unroll
    for (int i = 0; i < 8; i++)
#pragma unroll
        for (int k = 0; k < 4; k++) acc[i][k] = 0.f;

    for (int kc = 0; kc < 128; kc += 64) {
        // stage A chunk with bn+relu -> half
#pragma unroll
        for (int i = t; i < 2048; i += 256) {
            int r = i >> 4, kk = (i & 15) << 2;
            int row = row0 + r;
            float4 o = make_float4(0.f, 0.f, 0.f, 0.f);
            if (row < NN) {
                float4 hv = *(const float4*)(g_hidden + (size_t)row * 128 + kc + kk);
                float4 sc = *(const float4*)(g_scale + kc + kk);
                float4 sh = *(const float4*)(g_shift + kc + kk);
                o.x = fmaxf(fmaf(hv.x, sc.x, sh.x), 0.f);
                o.y = fmaxf(fmaf(hv.y, sc.y, sh.y), 0.f);
                o.z = fmaxf(fmaf(hv.z, sc.z, sh.z), 0.f);
                o.w = fmaxf(fmaf(hv.w, sc.w, sh.w), 0.f);
            }
            uint2 u;
            u.x = pack_h2(o.x, o.y);
            u.y = pack_h2(o.z, o.w);
            *(uint2*)(a_s + r * 72 + kk) = u;
        }
        // stage W chunk transposed: w_s[n][k] <- W[kc+k][n]
#pragma unroll
        for (int i = t; i < 1024; i += 256) {
            int n = i & 63, kb = (i >> 6) << 2;
            float v0 = W[(kc + kb + 0) * 64 + n];
            float v1 = W[(kc + kb + 1) * 64 + n];
            float v2 = W[(kc + kb + 2) * 64 + n];
            float v3 = W[(kc + kb + 3) * 64 + n];
            uint2 u;
            u.x = pack_h2(v0, v1);
            u.y = pack_h2(v2, v3);
            *(uint2*)(w_s + n * 72 + kb) = u;
        }
        __syncthreads();
#pragma unroll
        for (int ks = 0; ks < 64; ks += 16) {
            int n = n0w + g;
            unsigned b0 = *(unsigned*)(w_s + n * 72 + ks + 2 * q);
            unsigned b1 = *(unsigned*)(w_s + n * 72 + ks + 2 * q + 8);
#pragma unroll
            for (int mt = 0; mt < 8; mt++) {
                int r = mt * 16 + g;
                unsigned a0 = *(unsigned*)(a_s + r * 72 + ks + 2 * q);
                unsigned a1 = *(unsigned*)(a_s + (r + 8) * 72 + ks + 2 * q);
                unsigned a2 = *(unsigned*)(a_s + r * 72 + ks + 2 * q + 8);
                unsigned a3 = *(unsigned*)(a_s + (r + 8) * 72 + ks + 2 * q + 8);
                mma_f16(acc[mt], a0, a1, a2, a3, b0, b1);
            }
        }
        __syncthreads();
    }
    int c = n0w + 2 * q;
    float2 bv = *(const float2*)(bias + c);
#pragma unroll
    for (int mt = 0; mt < 8; mt++) {
        int rA = row0 + mt * 16 + g, rB = rA + 8;
        if (rA < NN) {
            float2 hv = *(float2*)(g_h + (size_t)rA * 64 + c);
            hv.x += acc[mt][0] + bv.x;
            hv.y += acc[mt][1] + bv.y;
            *(float2*)(g_h + (size_t)rA * 64 + c) = hv;
        }
        if (rB < NN) {
            float2 hv = *(float2*)(g_h + (size_t)rB * 64 + c);
            hv.x += acc[mt][2] + bv.x;
            hv.y += acc[mt][3] + bv.y;
            *(float2*)(g_h + (size_t)rB * 64 + c) = hv;
        }
    }
}

// ---------------- pool: run-length max over sorted batch + encoded atomicMax ----------------
__global__ void __launch_bounds__(256) k_pool(const int* __restrict__ batch) {
    int t = threadIdx.x;
    int c = t & 63, sub = t >> 6;
    int n0 = blockIdx.x * 64 + sub * 16;
    float cur = -__int_as_float(0x7f800000);  // -inf
    int curb = -1;
    for (int i = 0; i < 16; i++) {
        int n = n0 + i;
        if (n >= NN) break;
        int b = batch[n];
        if (b != curb) {
            if (curb >= 0) atomicMax(&g_pool[curb * 64 + c], encf(cur));
            curb = b;
            cur = -__int_as_float(0x7f800000);
        }
        cur = fmaxf(cur, g_h[n * 64 + c]);
    }
    if (curb >= 0) atomicMax(&g_pool[curb * 64 + c], encf(cur));
}

// ---------------- final MLP: [64,64] -> relu -> [64,80]; self-cleans g_pool ----------------
__global__ void __launch_bounds__(256) k_final(const float* __restrict__ w1,
                                               const float* __restrict__ b1,
                                               const float* __restrict__ w2,
                                               const float* __restrict__ b2,
                                               float* __restrict__ out) {
    __shared__ float g_s[64 * 64];
    __shared__ float t_s[64 * 64];
    int t = threadIdx.x;
    for (int i = t; i < 4096; i += 256) {
        unsigned u = g_pool[i];
        g_s[i] = (u == 0u) ? 0.f : decf(u);
        g_pool[i] = 0u;  // self-clean for next replay
    }
    __syncthreads();
    for (int e = t; e < 4096; e += 256) {
        int r = e >> 6, c = e & 63;
        float a = b1[c];
        for (int k = 0; k < 64; k++) a = fmaf(g_s[r * 64 + k], w1[k * 64 + c], a);
        t_s[e] = fmaxf(a, 0.f);
    }
    __syncthreads();
    for (int e = t; e < 5120; e += 256) {
        int r = e / 80, c = e % 80;
        float a = b2[c];
        for (int k = 0; k < 64; k++) a = fmaf(t_s[r * 64 + k], w2[k * 80 + c], a);
        out[e] = a;
    }
}

// ---------------- launch ----------------
extern "C" void kernel_launch(void* const* d_in, const int* in_sizes, int n_in,
                              void* d_out, int out_size) {
    const float* x    = (const float*)d_in[0];
    const int*   ei   = (const int*)d_in[1];
    const int*   batch = (const int*)d_in[2];
    const float* cw1  = (const float*)d_in[3];
    const float* cb1  = (const float*)d_in[4];
    const float* cg1  = (const float*)d_in[5];
    const float* cbe1 = (const float*)d_in[6];
    const float* cw2  = (const float*)d_in[7];
    const float* cb2  = (const float*)d_in[8];
    const float* Lw1  = (const float*)d_in[9];
    const float* Lb1  = (const float*)d_in[10];
    const float* Lg1  = (const float*)d_in[11];
    const float* Lbe1 = (const float*)d_in[12];
    const float* Lw2  = (const float*)d_in[13];
    const float* Lb2  = (const float*)d_in[14];
    const float* mw1  = (const float*)d_in[15];
    const float* mb1  = (const float*)d_in[16];
    const float* mw2  = (const float*)d_in[17];
    const float* mb2  = (const float*)d_in[18];
    float* out = (float*)d_out;

    const int* src = ei;
    const int* dst = ei + EE;

    // CSR build (g_deg starts zero; re-zeroed by k_scan3 each replay)
    k_deg<<<EE / 256, 256>>>(dst, x);
    k_scan1<<<98, 1024>>>();
    k_scan3<<<391, 256>>>();
    k_scatter<<<EE / 256, 256>>>(src, dst);

    // layer 0 (6 -> 12 -> 64), h = relu(genconv(x))
    k_l0<<<391, 256>>>(x, cw1, cb1, cg1, cbe1);
    k_l0_mlp2<<<391, 256>>>(cw2, cb2);

    // layers 1..3: h += genconv(relu(h))
    for (int i = 0; i < 3; i++) {
        k_agg64<<<12500, 256>>>();
        k_gemm1<<<782, 256>>>(Lw1 + i * 64 * 128, Lb1 + i * 128,
                              Lg1 + i * 128, Lbe1 + i * 128);
        k_gemm2<<<782, 256>>>(Lw2 + i * 128 * 64, Lb2 + i * 64);
    }

    k_pool<<<1563, 256>>>(batch);
    k_final<<<1, 256>>>(mw1, mb1, mw2, mb2, out);
}